// round 10
// baseline (speedup 1.0000x reference)
#include <cuda_runtime.h>
#include <cuda_bf16.h>
#include <cstdint>

#define NN   50000
#define EE   800000
#define KIN  512
#define NBLK 49

#define PB 256
#define PR 544

#define BM 128
#define BN 128
#define BK 32
#define NKT (KIN / BK)
#define STAGE_B 32768
#define GEMM_SMEM (3 * STAGE_B)

#define T_AH 0
#define T_AL 16384
#define T_BH 32768
#define T_BL 36864
#define T_STAGE 40960
#define TAIL_SMEM (2 * T_STAGE)

// ---------------- static device scratch ----------------
__device__ float g_bases[(size_t)NN * PB];
__device__ float g_agg[(size_t)NN * PB];
__device__ float g_rest[(size_t)NN * PR];
__device__ __nv_bfloat16 g_xhi[(size_t)NN * KIN];
__device__ __nv_bfloat16 g_xlo[(size_t)NN * KIN];
__device__ __nv_bfloat16 g_WhiT[(size_t)800 * KIN];
__device__ __nv_bfloat16 g_WloT[(size_t)800 * KIN];
__device__ float g_dinv[NN];
__device__ int   g_hist[NN];
__device__ int   g_rowstart[NN + 1];
__device__ int   g_cursor[NN];
__device__ int   g_csr[EE];
__device__ int   g_part[64];

// ---------------- helpers ----------------
__device__ __forceinline__ uint32_t smem_u32(const void* p) {
    uint32_t a;
    asm("{ .reg .u64 t; cvta.to.shared.u64 t, %1; cvt.u32.u64 %0, t; }" : "=r"(a) : "l"(p));
    return a;
}
__device__ __forceinline__ void ldmx4(uint32_t& r0, uint32_t& r1, uint32_t& r2, uint32_t& r3, uint32_t addr) {
    asm volatile("ldmatrix.sync.aligned.m8n8.x4.shared.b16 {%0,%1,%2,%3}, [%4];"
                 : "=r"(r0), "=r"(r1), "=r"(r2), "=r"(r3) : "r"(addr));
}
__device__ __forceinline__ void mma16816(float* c, const uint32_t* a, const uint32_t* b) {
    asm volatile(
        "mma.sync.aligned.m16n8k16.row.col.f32.bf16.bf16.f32 "
        "{%0,%1,%2,%3}, {%4,%5,%6,%7}, {%8,%9}, {%0,%1,%2,%3};"
        : "+f"(c[0]), "+f"(c[1]), "+f"(c[2]), "+f"(c[3])
        : "r"(a[0]), "r"(a[1]), "r"(a[2]), "r"(a[3]), "r"(b[0]), "r"(b[1]));
}
__device__ __forceinline__ void cpasync16(uint32_t dst, const void* src, bool pred) {
    int sz = pred ? 16 : 0;
    asm volatile("cp.async.cg.shared.global [%0], [%1], 16, %2;"
                 :: "r"(dst), "l"(src), "r"(sz) : "memory");
}
__device__ __forceinline__ void split8(const float* f, uint4& hi, uint4& lo) {
    uint32_t h[4], l[4];
    #pragma unroll
    for (int i = 0; i < 4; i++) {
        __nv_bfloat162 h2 = __float22bfloat162_rn(make_float2(f[2 * i], f[2 * i + 1]));
        float r0 = f[2 * i]     - __bfloat162float(__low2bfloat16(h2));
        float r1 = f[2 * i + 1] - __bfloat162float(__high2bfloat16(h2));
        __nv_bfloat162 l2 = __float22bfloat162_rn(make_float2(r0, r1));
        h[i] = *(uint32_t*)&h2;
        l[i] = *(uint32_t*)&l2;
    }
    hi = make_uint4(h[0], h[1], h[2], h[3]);
    lo = make_uint4(l[0], l[1], l[2], l[3]);
}

// ---------------- graph prep ----------------
__global__ void k_zero() {
    int i = blockIdx.x * blockDim.x + threadIdx.x;
    if (i < NN) { g_hist[i] = 0; g_cursor[i] = 0; }
}
__global__ void k_hist(const int* __restrict__ ei) {
    int e = blockIdx.x * blockDim.x + threadIdx.x;
    if (e < EE) atomicAdd(&g_hist[ei[EE + e]], 1);
}
__global__ void k_dinv() {
    int i = blockIdx.x * blockDim.x + threadIdx.x;
    if (i < NN) g_dinv[i] = rsqrtf((float)(g_hist[i] + 1));
}
__global__ void k_scan1() {
    __shared__ int s[1024];
    int b = blockIdx.x, t = threadIdx.x, i = b * 1024 + t;
    int v = (i < NN) ? g_hist[i] : 0;
    int x = v; s[t] = x; __syncthreads();
    #pragma unroll
    for (int off = 1; off < 1024; off <<= 1) {
        int tmp = (t >= off) ? s[t - off] : 0;
        __syncthreads();
        x += tmp; s[t] = x;
        __syncthreads();
    }
    if (i < NN) g_rowstart[i] = x - v;
    if (t == 1023) g_part[b] = x;
}
__global__ void k_scan2() {
    __shared__ int s[64];
    int t = threadIdx.x;
    int v = (t < NBLK) ? g_part[t] : 0;
    int x = v; s[t] = x; __syncthreads();
    #pragma unroll
    for (int off = 1; off < 64; off <<= 1) {
        int tmp = (t >= off) ? s[t - off] : 0;
        __syncthreads();
        x += tmp; s[t] = x;
        __syncthreads();
    }
    if (t < NBLK) g_part[t] = x - v;
    if (t == 63) g_rowstart[NN] = s[63];
}
__global__ void k_scan3() {
    int b = blockIdx.x, i = b * 1024 + threadIdx.x;
    if (i < NN) g_rowstart[i] += g_part[b];
}
__global__ void k_fill(const int* __restrict__ ei) {
    int e = blockIdx.x * blockDim.x + threadIdx.x;
    if (e < EE) {
        int d = ei[EE + e];
        int p = atomicAdd(&g_cursor[d], 1);
        g_csr[g_rowstart[d] + p] = ei[e];
    }
}
__global__ void k_packT(const float* __restrict__ Wb, const float* __restrict__ Wc,
                        const float* __restrict__ Wr) {
    int idx = blockIdx.x * blockDim.x + threadIdx.x;
    if (idx >= 800 * KIN) return;
    int n = idx / KIN, k = idx % KIN;
    float v;
    if (n < 256)      v = Wb[k * 256 + n];
    else if (n < 288) v = Wc[k * 32 + (n - 256)];
    else              v = Wr[k * 512 + (n - 288)];
    __nv_bfloat16 h = __float2bfloat16(v);
    g_WhiT[idx] = h;
    g_WloT[idx] = __float2bfloat16(v - __bfloat162float(h));
}
__global__ void k_split(const float* __restrict__ x) {
    size_t i = (size_t)blockIdx.x * blockDim.x + threadIdx.x;
    if (i >= (size_t)NN * KIN / 4) return;
    float4 v = ((const float4*)x)[i];
    float f[4] = {v.x, v.y, v.z, v.w};
    uint32_t h[2], l[2];
    #pragma unroll
    for (int q = 0; q < 2; q++) {
        __nv_bfloat162 h2 = __float22bfloat162_rn(make_float2(f[2 * q], f[2 * q + 1]));
        float r0 = f[2 * q]     - __bfloat162float(__low2bfloat16(h2));
        float r1 = f[2 * q + 1] - __bfloat162float(__high2bfloat16(h2));
        __nv_bfloat162 l2 = __float22bfloat162_rn(make_float2(r0, r1));
        h[q] = *(uint32_t*)&h2;
        l[q] = *(uint32_t*)&l2;
    }
    ((uint2*)g_xhi)[i] = make_uint2(h[0], h[1]);
    ((uint2*)g_xlo)[i] = make_uint2(l[0], l[1]);
}

// ---------------- main HMMA GEMM (wave version, round-8 proven): mode 0 = bases cols[0,256),
// mode 1 = rest cols[256,768) -> g_rest cols [0,512). cp.async 3-stage, 2 CTAs/SM. ----------------
__global__ void __launch_bounds__(256, 2) k_gemm_main(int mode) {
    extern __shared__ char smem[];
    uint32_t sb = smem_u32(smem);
    int tid = threadIdx.x, wid = tid >> 5, lane = tid & 31;
    int m0 = blockIdx.y * BM, n0 = blockIdx.x * BN;
    int wm = wid & 1, wn = wid >> 1;

    float* dst = (mode == 0) ? g_bases : g_rest;
    int pitch  = (mode == 0) ? PB : PR;
    int nsrc0  = (mode == 0) ? 0 : 256;

    float acc[4][4][4];
    #pragma unroll
    for (int i = 0; i < 4; i++)
        #pragma unroll
        for (int j = 0; j < 4; j++)
            #pragma unroll
            for (int q = 0; q < 4; q++) acc[i][j][q] = 0.f;

    int sr = tid >> 3, sc = tid & 7;
    const __nv_bfloat16* aSrc = (sc < 4) ? g_xhi : g_xlo;
    const __nv_bfloat16* bSrc = (sc < 4) ? g_WhiT : g_WloT;
    int koff = (sc & 3) * 8;
    uint32_t st_off[4];
    bool arow_ok[4];
    #pragma unroll
    for (int i = 0; i < 4; i++) {
        int r = sr + i * 32;
        st_off[i] = (uint32_t)(r * 128 + ((sc ^ (r & 7)) * 16));
        arow_ok[i] = (m0 + r) < NN;
    }

    int a_row[4];
    #pragma unroll
    for (int mt = 0; mt < 4; mt++) a_row[mt] = wm * 64 + mt * 16 + (lane & 15);
    int a_lc = lane >> 4;
    int b_row0 = wn * 32 + ((lane >> 4) << 3) + (lane & 7);
    int b_row1 = b_row0 + 16;
    int b_lc = (lane >> 3) & 1;

    auto issue = [&](int s, int buf) {
        int k0 = s * BK;
        uint32_t base = sb + buf * STAGE_B;
        #pragma unroll
        for (int i = 0; i < 4; i++) {
            const void* src = aSrc + (size_t)(m0 + sr + i * 32) * KIN + k0 + koff;
            cpasync16(base + st_off[i], src, arow_ok[i]);
        }
        #pragma unroll
        for (int i = 0; i < 4; i++) {
            const void* src = bSrc + (size_t)(nsrc0 + n0 + sr + i * 32) * KIN + k0 + koff;
            cpasync16(base + 16384 + st_off[i], src, true);
        }
        asm volatile("cp.async.commit_group;" ::: "memory");
    };

    issue(0, 0);
    issue(1, 1);

    int cbuf = 0, nbuf = 2;
    #pragma unroll 1
    for (int kt = 0; kt < NKT; kt++) {
        if (kt < NKT - 1) asm volatile("cp.async.wait_group 1;" ::: "memory");
        else              asm volatile("cp.async.wait_group 0;" ::: "memory");
        __syncthreads();

        if (kt + 2 < NKT) {
            issue(kt + 2, nbuf);
        } else {
            asm volatile("cp.async.commit_group;" ::: "memory");
        }

        uint32_t ab = sb + cbuf * STAGE_B;
        uint32_t bb = ab + 16384;

        #pragma unroll
        for (int g = 0; g < 2; g++) {
            uint32_t bhf[8], blf[8];
            {
                int ch = g * 2 + b_lc;
                uint32_t o0h = (uint32_t)(b_row0 * 128 + ((ch ^ (b_row0 & 7)) * 16));
                uint32_t o1h = (uint32_t)(b_row1 * 128 + ((ch ^ (b_row1 & 7)) * 16));
                uint32_t o0l = (uint32_t)(b_row0 * 128 + (((ch + 4) ^ (b_row0 & 7)) * 16));
                uint32_t o1l = (uint32_t)(b_row1 * 128 + (((ch + 4) ^ (b_row1 & 7)) * 16));
                ldmx4(bhf[0], bhf[1], bhf[2], bhf[3], bb + o0h);
                ldmx4(bhf[4], bhf[5], bhf[6], bhf[7], bb + o1h);
                ldmx4(blf[0], blf[1], blf[2], blf[3], bb + o0l);
                ldmx4(blf[4], blf[5], blf[6], blf[7], bb + o1l);
            }
            #pragma unroll
            for (int mt = 0; mt < 4; mt++) {
                uint32_t ahf[4], alf[4];
                int r = a_row[mt];
                int ch = g * 2 + a_lc;
                uint32_t oh = (uint32_t)(r * 128 + ((ch ^ (r & 7)) * 16));
                uint32_t ol = (uint32_t)(r * 128 + (((ch + 4) ^ (r & 7)) * 16));
                ldmx4(ahf[0], ahf[1], ahf[2], ahf[3], ab + oh);
                ldmx4(alf[0], alf[1], alf[2], alf[3], ab + ol);
                #pragma unroll
                for (int nt = 0; nt < 4; nt++) {
                    mma16816(acc[mt][nt], ahf, &bhf[nt * 2]);
                    mma16816(acc[mt][nt], ahf, &blf[nt * 2]);
                    mma16816(acc[mt][nt], alf, &bhf[nt * 2]);
                }
            }
        }

        cbuf = (cbuf == 2) ? 0 : cbuf + 1;
        nbuf = (nbuf == 2) ? 0 : nbuf + 1;
    }

    int gid = lane >> 2, tig = lane & 3;
    #pragma unroll
    for (int mt = 0; mt < 4; mt++) {
        int row0 = m0 + wm * 64 + mt * 16 + gid;
        #pragma unroll
        for (int nt = 0; nt < 4; nt++) {
            int col = n0 + wn * 32 + nt * 8 + 2 * tig;
            if (row0 < NN)
                *(float2*)(dst + (size_t)row0 * pitch + col) = make_float2(acc[mt][nt][0], acc[mt][nt][1]);
            if (row0 + 8 < NN)
                *(float2*)(dst + (size_t)(row0 + 8) * pitch + col) = make_float2(acc[mt][nt][2], acc[mt][nt][3]);
        }
    }
}

// ---------------- tail HMMA GEMM: orig cols [768,800) -> g_rest cols [512,544) ----------------
__global__ void __launch_bounds__(256, 2) k_gemm_tail(const float* __restrict__ x) {
    extern __shared__ char smem[];
    uint32_t sb = smem_u32(smem);
    int tid = threadIdx.x, wid = tid >> 5, lane = tid & 31;
    int m0 = blockIdx.x * BM;
    const int n0 = 768;
    int wm = wid & 1, wn = wid >> 1;

    float acc[4][4];
    #pragma unroll
    for (int i = 0; i < 4; i++)
        #pragma unroll
        for (int q = 0; q < 4; q++) acc[i][q] = 0.f;

    int sr = tid >> 3, sc = tid & 7;
    const bool arow_ok[4] = { (m0 + sr) < NN, (m0 + sr + 32) < NN,
                              (m0 + sr + 64) < NN, (m0 + sr + 96) < NN };
    uint32_t st_off[4];
    #pragma unroll
    for (int v = 0; v < 4; v++) {
        int r = sr + v * 32;
        st_off[v] = (uint32_t)(r * 128 + ((sc ^ (r & 7)) * 16));
    }
    uint32_t bst_off = (uint32_t)(sr * 128 + ((sc ^ (sr & 7)) * 16));

    int a_row[4];
    #pragma unroll
    for (int mt = 0; mt < 4; mt++) a_row[mt] = wm * 64 + mt * 16 + (lane & 15);
    int a_lc = lane >> 4;
    int b_rw = wn * 8 + (lane & 7);
    int b_ms = lane >> 3;

    {
        #pragma unroll
        for (int v = 0; v < 4; v++) {
            float f[8];
            if (arow_ok[v]) {
                const float* p = x + (size_t)(m0 + sr + v * 32) * KIN + sc * 8;
                *(float4*)&f[0] = *(const float4*)p;
                *(float4*)&f[4] = *(const float4*)(p + 4);
            } else {
                #pragma unroll
                for (int q = 0; q < 8; q++) f[q] = 0.f;
            }
            uint4 hi, lo; split8(f, hi, lo);
            *(uint4*)(smem + T_AH + st_off[v]) = hi;
            *(uint4*)(smem + T_AL + st_off[v]) = lo;
        }
        size_t off = (size_t)(n0 + sr) * KIN + sc * 8;
        *(uint4*)(smem + T_BH + bst_off) = *(const uint4*)(g_WhiT + off);
        *(uint4*)(smem + T_BL + bst_off) = *(const uint4*)(g_WloT + off);
    }
    __syncthreads();

    #pragma unroll 1
    for (int kt = 0; kt < KIN / 64; kt++) {
        int cur = kt & 1;
        bool more = (kt + 1) < (KIN / 64);

        float pa[4][8];
        uint4 pbh, pbl;
        if (more) {
            int k0 = (kt + 1) * 64;
            #pragma unroll
            for (int v = 0; v < 4; v++) {
                if (arow_ok[v]) {
                    const float* p = x + (size_t)(m0 + sr + v * 32) * KIN + k0 + sc * 8;
                    *(float4*)&pa[v][0] = *(const float4*)p;
                    *(float4*)&pa[v][4] = *(const float4*)(p + 4);
                } else {
                    #pragma unroll
                    for (int q = 0; q < 8; q++) pa[v][q] = 0.f;
                }
            }
            size_t off = (size_t)(n0 + sr) * KIN + k0 + sc * 8;
            pbh = *(const uint4*)(g_WhiT + off);
            pbl = *(const uint4*)(g_WloT + off);
        }

        uint32_t ah_b = sb + cur * T_STAGE + T_AH;
        uint32_t al_b = sb + cur * T_STAGE + T_AL;
        uint32_t bh_b = sb + cur * T_STAGE + T_BH;
        uint32_t bl_b = sb + cur * T_STAGE + T_BL;

        #pragma unroll
        for (int p = 0; p < 2; p++) {
            uint32_t bhf[4], blf[4];
            uint32_t boff = (uint32_t)(b_rw * 128 + (((4 * p + b_ms) ^ (b_rw & 7)) * 16));
            ldmx4(bhf[0], bhf[1], bhf[2], bhf[3], bh_b + boff);
            ldmx4(blf[0], blf[1], blf[2], blf[3], bl_b + boff);
            #pragma unroll
            for (int s = 0; s < 2; s++) {
                int k16 = 2 * p + s;
                uint32_t ahf[4][4], alf[4][4];
                #pragma unroll
                for (int mt = 0; mt < 4; mt++) {
                    int r = a_row[mt];
                    uint32_t off = (uint32_t)(r * 128 + (((k16 * 2 + a_lc) ^ (r & 7)) * 16));
                    ldmx4(ahf[mt][0], ahf[mt][1], ahf[mt][2], ahf[mt][3], ah_b + off);
                    ldmx4(alf[mt][0], alf[mt][1], alf[mt][2], alf[mt][3], al_b + off);
                }
                #pragma unroll
                for (int mt = 0; mt < 4; mt++) {
                    mma16816(acc[mt], ahf[mt], &bhf[2 * s]);
                    mma16816(acc[mt], ahf[mt], &blf[2 * s]);
                    mma16816(acc[mt], alf[mt], &bhf[2 * s]);
                }
            }
        }

        if (more) {
            char* dst = smem + (cur ^ 1) * T_STAGE;
            #pragma unroll
            for (int v = 0; v < 4; v++) {
                uint4 hi, lo; split8(pa[v], hi, lo);
                *(uint4*)(dst + T_AH + st_off[v]) = hi;
                *(uint4*)(dst + T_AL + st_off[v]) = lo;
            }
            *(uint4*)(dst + T_BH + bst_off) = pbh;
            *(uint4*)(dst + T_BL + bst_off) = pbl;
        }
        __syncthreads();
    }

    int gid = lane >> 2, tig = lane & 3;
    #pragma unroll
    for (int mt = 0; mt < 4; mt++) {
        int row0 = m0 + wm * 64 + mt * 16 + gid;
        int col = 512 + wn * 8 + 2 * tig;
        if (row0 < NN)
            *(float2*)(g_rest + (size_t)row0 * PR + col) = make_float2(acc[mt][0], acc[mt][1]);
        if (row0 + 8 < NN)
            *(float2*)(g_rest + (size_t)(row0 + 8) * PR + col) = make_float2(acc[mt][2], acc[mt][3]);
    }
}

// ---------------- aggregation: gather bases -> g_agg (64 thr/node, round-8 gather core) ----------------
__global__ void __launch_bounds__(64) k_agg() {
    int n = blockIdx.x;
    int t = threadIdx.x;

    __shared__ int   s_src[64];
    __shared__ float s_wt[64];

    float dn = g_dinv[n];
    const float* Bn = g_bases + (size_t)n * PB;

    float4 acc = ((const float4*)Bn)[t];
    float dn2 = dn * dn;
    acc.x *= dn2; acc.y *= dn2; acc.z *= dn2; acc.w *= dn2;

    int start = g_rowstart[n];
    int end   = g_rowstart[n + 1];
    for (int base = start; base < end; base += 64) {
        int cnt = min(64, end - base);
        if (t < cnt) {
            int s = g_csr[base + t];
            s_src[t] = s;
            s_wt[t]  = g_dinv[s] * dn;
        }
        __syncthreads();
        int j = 0;
        for (; j + 4 <= cnt; j += 4) {
            float4 v0 = ((const float4*)(g_bases + (size_t)s_src[j]     * PB))[t];
            float4 v1 = ((const float4*)(g_bases + (size_t)s_src[j + 1] * PB))[t];
            float4 v2 = ((const float4*)(g_bases + (size_t)s_src[j + 2] * PB))[t];
            float4 v3 = ((const float4*)(g_bases + (size_t)s_src[j + 3] * PB))[t];
            float w0 = s_wt[j], w1 = s_wt[j + 1], w2 = s_wt[j + 2], w3 = s_wt[j + 3];
            acc.x = fmaf(v0.x, w0, acc.x); acc.y = fmaf(v0.y, w0, acc.y);
            acc.z = fmaf(v0.z, w0, acc.z); acc.w = fmaf(v0.w, w0, acc.w);
            acc.x = fmaf(v1.x, w1, acc.x); acc.y = fmaf(v1.y, w1, acc.y);
            acc.z = fmaf(v1.z, w1, acc.z); acc.w = fmaf(v1.w, w1, acc.w);
            acc.x = fmaf(v2.x, w2, acc.x); acc.y = fmaf(v2.y, w2, acc.y);
            acc.z = fmaf(v2.z, w2, acc.z); acc.w = fmaf(v2.w, w2, acc.w);
            acc.x = fmaf(v3.x, w3, acc.x); acc.y = fmaf(v3.y, w3, acc.y);
            acc.z = fmaf(v3.z, w3, acc.z); acc.w = fmaf(v3.w, w3, acc.w);
        }
        for (; j < cnt; j++) {
            float4 v = ((const float4*)(g_bases + (size_t)s_src[j] * PB))[t];
            float w = s_wt[j];
            acc.x = fmaf(v.x, w, acc.x); acc.y = fmaf(v.y, w, acc.y);
            acc.z = fmaf(v.z, w, acc.z); acc.w = fmaf(v.w, w, acc.w);
        }
        __syncthreads();
    }

    ((float4*)(g_agg + (size_t)n * PB))[t] = acc;
}

// ---------------- epilogue: combine + residual + LayerNorm + ReLU ----------------
__global__ void __launch_bounds__(64) k_epi(
    const float* __restrict__ bcomb, const float* __restrict__ convb,
    const float* __restrict__ bres,  const float* __restrict__ gamma,
    const float* __restrict__ beta,  float* __restrict__ out)
{
    int n = blockIdx.x;
    int t = threadIdx.x;

    __shared__ float s_agg[4 * 65];
    __shared__ float s_w[32];
    __shared__ float s_red[4];

    const float* An = g_agg  + (size_t)n * PB;
    const float* Rn = g_rest + (size_t)n * PR;

    {
        float4 a = ((const float4*)An)[t];
        int c0 = t * 4, b = c0 >> 6, f = c0 & 63;
        float* p = &s_agg[b * 65 + f];
        p[0] = a.x; p[1] = a.y; p[2] = a.z; p[3] = a.w;
    }
    if (t < 32) s_w[t] = Rn[t] + bcomb[t];
    __syncthreads();

    int o0 = t * 8;
    int h  = t >> 3;
    int f0 = (t & 7) * 8;
    float w0 = s_w[h * 4 + 0], w1 = s_w[h * 4 + 1];
    float w2 = s_w[h * 4 + 2], w3 = s_w[h * 4 + 3];

    float res[8], cbv[8], brv[8];
    *(float4*)&res[0] = *(const float4*)(Rn + 32 + o0);
    *(float4*)&res[4] = *(const float4*)(Rn + 32 + o0 + 4);
    *(float4*)&cbv[0] = *(const float4*)(convb + o0);
    *(float4*)&cbv[4] = *(const float4*)(convb + o0 + 4);
    *(float4*)&brv[0] = *(const float4*)(bres + o0);
    *(float4*)&brv[4] = *(const float4*)(bres + o0 + 4);

    float v[8];
    float sum = 0.f, sq = 0.f;
    #pragma unroll
    for (int j = 0; j < 8; j++) {
        int f = f0 + j;
        float c = w0 * s_agg[f] + w1 * s_agg[65 + f] + w2 * s_agg[130 + f] + w3 * s_agg[195 + f];
        c += cbv[j] + res[j] + brv[j];
        v[j] = c;
        sum += c;
        sq = fmaf(c, c, sq);
    }

    #pragma unroll
    for (int off = 16; off; off >>= 1) {
        sum += __shfl_xor_sync(0xffffffffu, sum, off);
        sq  += __shfl_xor_sync(0xffffffffu, sq, off);
    }
    if ((t & 31) == 0) { s_red[t >> 5] = sum; s_red[2 + (t >> 5)] = sq; }
    __syncthreads();
    sum = s_red[0] + s_red[1];
    sq  = s_red[2] + s_red[3];

    float mean = sum * (1.0f / 512.0f);
    float var  = sq * (1.0f / 512.0f) - mean * mean;
    float rstd = rsqrtf(var + 1e-5f);

    float gm[8], bt[8], o[8];
    *(float4*)&gm[0] = *(const float4*)(gamma + o0);
    *(float4*)&gm[4] = *(const float4*)(gamma + o0 + 4);
    *(float4*)&bt[0] = *(const float4*)(beta + o0);
    *(float4*)&bt[4] = *(const float4*)(beta + o0 + 4);
    #pragma unroll
    for (int j = 0; j < 8; j++)
        o[j] = fmaxf(0.f, (v[j] - mean) * rstd * gm[j] + bt[j]);
    float* op = out + (size_t)n * 512 + o0;
    *(float4*)op       = *(float4*)&o[0];
    *(float4*)(op + 4) = *(float4*)&o[4];
}

// ---------------- launch (fork/join DAG, graph-capturable) ----------------
extern "C" void kernel_launch(void* const* d_in, const int* in_sizes, int n_in,
                              void* d_out, int out_size) {
    const float* x  = (const float*)d_in[0];
    const int*   ei = (const int*)d_in[1];
    const float* Wb = (const float*)d_in[2];
    const float* Wc = (const float*)d_in[3];
    const float* bc = (const float*)d_in[4];
    const float* cb = (const float*)d_in[5];
    const float* Wr = (const float*)d_in[6];
    const float* br = (const float*)d_in[7];
    const float* gm = (const float*)d_in[8];
    const float* bt = (const float*)d_in[9];
    float* out = (float*)d_out;

    static cudaStream_t s1 = nullptr, s2 = nullptr;
    static cudaEvent_t  ev0 = nullptr, evP = nullptr, evB = nullptr, ev1 = nullptr, ev2 = nullptr;
    static bool init = false;
    if (!init) {
        cudaStreamCreateWithFlags(&s1, cudaStreamNonBlocking);
        cudaStreamCreateWithFlags(&s2, cudaStreamNonBlocking);
        cudaEventCreateWithFlags(&ev0, cudaEventDisableTiming);
        cudaEventCreateWithFlags(&evP, cudaEventDisableTiming);
        cudaEventCreateWithFlags(&evB, cudaEventDisableTiming);
        cudaEventCreateWithFlags(&ev1, cudaEventDisableTiming);
        cudaEventCreateWithFlags(&ev2, cudaEventDisableTiming);
        cudaFuncSetAttribute(k_gemm_main, cudaFuncAttributeMaxDynamicSharedMemorySize, GEMM_SMEM);
        cudaFuncSetAttribute(k_gemm_tail, cudaFuncAttributeMaxDynamicSharedMemorySize, TAIL_SMEM);
        init = true;
    }

    // fork
    cudaEventRecord(ev0, 0);
    cudaStreamWaitEvent(s1, ev0, 0);
    cudaStreamWaitEvent(s2, ev0, 0);

    k_packT<<<(800 * KIN + 255) / 256, 256, 0, s1>>>(Wb, Wc, Wr);           // idx 0
    cudaEventRecord(evP, s1);

    k_split<<<(NN * KIN / 4 + 255) / 256, 256>>>(x);                        // idx 1 (main)
    k_gemm_tail<<<(NN + BM - 1) / BM, 256, TAIL_SMEM, s1>>>(x);             // idx 2 (s1)

    cudaStreamWaitEvent(0, evP, 0);      // GEMMs need packed weights
    dim3 gb(2, (NN + BM - 1) / BM);
    k_gemm_main<<<gb, 256, GEMM_SMEM>>>(0);                                 // idx 3 (profiled) — bases
    cudaEventRecord(evB, 0);

    dim3 gr(4, (NN + BM - 1) / BM);
    k_gemm_main<<<gr, 256, GEMM_SMEM>>>(1);                                 // idx 4 — rest (main)

    // prep chain on s2, then aggregation once bases are ready
    k_zero<<<(NN + 255) / 256, 256, 0, s2>>>();                             // idx 5
    k_hist<<<(EE + 255) / 256, 256, 0, s2>>>(ei);                           // idx 6
    k_dinv<<<(NN + 255) / 256, 256, 0, s2>>>();                             // idx 7
    k_scan1<<<NBLK, 1024, 0, s2>>>();                                       // idx 8
    k_scan2<<<1, 64, 0, s2>>>();                                            // idx 9
    k_scan3<<<NBLK, 1024, 0, s2>>>();                                       // idx 10
    k_fill<<<(EE + 255) / 256, 256, 0, s2>>>(ei);                           // idx 11
    cudaStreamWaitEvent(s2, evB, 0);
    k_agg<<<NN, 64, 0, s2>>>();                                             // idx 12 — overlaps rest-GEMM

    // join
    cudaEventRecord(ev1, s1);
    cudaEventRecord(ev2, s2);
    cudaStreamWaitEvent(0, ev1, 0);
    cudaStreamWaitEvent(0, ev2, 0);

    k_epi<<<NN, 64>>>(bc, cb, br, gm, bt, out);                             // idx 13
}

// round 11
// speedup vs baseline: 1.0552x; 1.0552x over previous
#include <cuda_runtime.h>
#include <cuda_bf16.h>
#include <cstdint>

#define NN   50000
#define EE   800000
#define KIN  512
#define NBLK 49

#define PB 256              // bases cols (bf16 slab)
#define PR 544              // rest: [0,32) comb | [32,544) res (fp32)

#define BM 128
#define BN 128
#define BK 32
#define NKT (KIN / BK)
#define NTILES_N 6
#define STAGE_B 32768
#define GEMM_SMEM (3 * STAGE_B)

#define T_AH 0
#define T_AL 16384
#define T_BH 32768
#define T_BL 36864
#define T_STAGE 40960
#define TAIL_SMEM (2 * T_STAGE)

// ---------------- static device scratch ----------------
__device__ __nv_bfloat16 g_bases_bf[(size_t)NN * PB];   // 25.6 MB bf16 gather slab
__device__ float g_rest[(size_t)NN * PR];
__device__ __nv_bfloat16 g_xhi[(size_t)NN * KIN];
__device__ __nv_bfloat16 g_xlo[(size_t)NN * KIN];
__device__ __nv_bfloat16 g_WhiT[(size_t)800 * KIN];
__device__ __nv_bfloat16 g_WloT[(size_t)800 * KIN];
__device__ float g_dinv[NN];
__device__ int   g_hist[NN];
__device__ int   g_rowstart[NN + 1];
__device__ int   g_cursor[NN];
__device__ int   g_csr[EE];
__device__ int   g_part[64];

// ---------------- helpers ----------------
__device__ __forceinline__ uint32_t smem_u32(const void* p) {
    uint32_t a;
    asm("{ .reg .u64 t; cvta.to.shared.u64 t, %1; cvt.u32.u64 %0, t; }" : "=r"(a) : "l"(p));
    return a;
}
__device__ __forceinline__ void ldmx4(uint32_t& r0, uint32_t& r1, uint32_t& r2, uint32_t& r3, uint32_t addr) {
    asm volatile("ldmatrix.sync.aligned.m8n8.x4.shared.b16 {%0,%1,%2,%3}, [%4];"
                 : "=r"(r0), "=r"(r1), "=r"(r2), "=r"(r3) : "r"(addr));
}
__device__ __forceinline__ void mma16816(float* c, const uint32_t* a, const uint32_t* b) {
    asm volatile(
        "mma.sync.aligned.m16n8k16.row.col.f32.bf16.bf16.f32 "
        "{%0,%1,%2,%3}, {%4,%5,%6,%7}, {%8,%9}, {%0,%1,%2,%3};"
        : "+f"(c[0]), "+f"(c[1]), "+f"(c[2]), "+f"(c[3])
        : "r"(a[0]), "r"(a[1]), "r"(a[2]), "r"(a[3]), "r"(b[0]), "r"(b[1]));
}
__device__ __forceinline__ void cpasync16(uint32_t dst, const void* src, bool pred) {
    int sz = pred ? 16 : 0;
    asm volatile("cp.async.cg.shared.global [%0], [%1], 16, %2;"
                 :: "r"(dst), "l"(src), "r"(sz) : "memory");
}
__device__ __forceinline__ void split8(const float* f, uint4& hi, uint4& lo) {
    uint32_t h[4], l[4];
    #pragma unroll
    for (int i = 0; i < 4; i++) {
        __nv_bfloat162 h2 = __float22bfloat162_rn(make_float2(f[2 * i], f[2 * i + 1]));
        float r0 = f[2 * i]     - __bfloat162float(__low2bfloat16(h2));
        float r1 = f[2 * i + 1] - __bfloat162float(__high2bfloat16(h2));
        __nv_bfloat162 l2 = __float22bfloat162_rn(make_float2(r0, r1));
        h[i] = *(uint32_t*)&h2;
        l[i] = *(uint32_t*)&l2;
    }
    hi = make_uint4(h[0], h[1], h[2], h[3]);
    lo = make_uint4(l[0], l[1], l[2], l[3]);
}

// ---------------- graph prep ----------------
__global__ void k_zero() {
    int i = blockIdx.x * blockDim.x + threadIdx.x;
    if (i < NN) { g_hist[i] = 0; g_cursor[i] = 0; }
}
__global__ void k_hist(const int* __restrict__ ei) {
    int e = blockIdx.x * blockDim.x + threadIdx.x;
    if (e < EE) atomicAdd(&g_hist[ei[EE + e]], 1);
}
__global__ void k_dinv() {
    int i = blockIdx.x * blockDim.x + threadIdx.x;
    if (i < NN) g_dinv[i] = rsqrtf((float)(g_hist[i] + 1));
}
__global__ void k_scan1() {
    __shared__ int s[1024];
    int b = blockIdx.x, t = threadIdx.x, i = b * 1024 + t;
    int v = (i < NN) ? g_hist[i] : 0;
    int x = v; s[t] = x; __syncthreads();
    #pragma unroll
    for (int off = 1; off < 1024; off <<= 1) {
        int tmp = (t >= off) ? s[t - off] : 0;
        __syncthreads();
        x += tmp; s[t] = x;
        __syncthreads();
    }
    if (i < NN) g_rowstart[i] = x - v;
    if (t == 1023) g_part[b] = x;
}
__global__ void k_scan2() {
    __shared__ int s[64];
    int t = threadIdx.x;
    int v = (t < NBLK) ? g_part[t] : 0;
    int x = v; s[t] = x; __syncthreads();
    #pragma unroll
    for (int off = 1; off < 64; off <<= 1) {
        int tmp = (t >= off) ? s[t - off] : 0;
        __syncthreads();
        x += tmp; s[t] = x;
        __syncthreads();
    }
    if (t < NBLK) g_part[t] = x - v;
    if (t == 63) g_rowstart[NN] = s[63];
}
__global__ void k_scan3() {
    int b = blockIdx.x, i = b * 1024 + threadIdx.x;
    if (i < NN) g_rowstart[i] += g_part[b];
}
__global__ void k_fill(const int* __restrict__ ei) {
    int e = blockIdx.x * blockDim.x + threadIdx.x;
    if (e < EE) {
        int d = ei[EE + e];
        int p = atomicAdd(&g_cursor[d], 1);
        g_csr[g_rowstart[d] + p] = ei[e];
    }
}
__global__ void k_packT(const float* __restrict__ Wb, const float* __restrict__ Wc,
                        const float* __restrict__ Wr) {
    int idx = blockIdx.x * blockDim.x + threadIdx.x;
    if (idx >= 800 * KIN) return;
    int n = idx / KIN, k = idx % KIN;
    float v;
    if (n < 256)      v = Wb[k * 256 + n];
    else if (n < 288) v = Wc[k * 32 + (n - 256)];
    else              v = Wr[k * 512 + (n - 288)];
    __nv_bfloat16 h = __float2bfloat16(v);
    g_WhiT[idx] = h;
    g_WloT[idx] = __float2bfloat16(v - __bfloat162float(h));
}
__global__ void k_split(const float* __restrict__ x) {
    size_t i = (size_t)blockIdx.x * blockDim.x + threadIdx.x;
    if (i >= (size_t)NN * KIN / 4) return;
    float4 v = ((const float4*)x)[i];
    float f[4] = {v.x, v.y, v.z, v.w};
    uint32_t h[2], l[2];
    #pragma unroll
    for (int q = 0; q < 2; q++) {
        __nv_bfloat162 h2 = __float22bfloat162_rn(make_float2(f[2 * q], f[2 * q + 1]));
        float r0 = f[2 * q]     - __bfloat162float(__low2bfloat16(h2));
        float r1 = f[2 * q + 1] - __bfloat162float(__high2bfloat16(h2));
        __nv_bfloat162 l2 = __float22bfloat162_rn(make_float2(r0, r1));
        h[q] = *(uint32_t*)&h2;
        l[q] = *(uint32_t*)&l2;
    }
    ((uint2*)g_xhi)[i] = make_uint2(h[0], h[1]);
    ((uint2*)g_xlo)[i] = make_uint2(l[0], l[1]);
}

// ---------------- main HMMA GEMM (round-8 wave version): cols [0,768) ----------------
// cols [0,256) -> g_bases_bf (bf16), cols [256,768) -> g_rest[0,512) (fp32)
__global__ void __launch_bounds__(256, 2) k_gemm_mma() {
    extern __shared__ char smem[];
    uint32_t sb = smem_u32(smem);
    int tid = threadIdx.x, wid = tid >> 5, lane = tid & 31;
    int m0 = blockIdx.y * BM, n0 = blockIdx.x * BN;
    int wm = wid & 1, wn = wid >> 1;

    float acc[4][4][4];
    #pragma unroll
    for (int i = 0; i < 4; i++)
        #pragma unroll
        for (int j = 0; j < 4; j++)
            #pragma unroll
            for (int q = 0; q < 4; q++) acc[i][j][q] = 0.f;

    int sr = tid >> 3, sc = tid & 7;
    const __nv_bfloat16* aSrc = (sc < 4) ? g_xhi : g_xlo;
    const __nv_bfloat16* bSrc = (sc < 4) ? g_WhiT : g_WloT;
    int koff = (sc & 3) * 8;
    uint32_t st_off[4];
    bool arow_ok[4];
    #pragma unroll
    for (int i = 0; i < 4; i++) {
        int r = sr + i * 32;
        st_off[i] = (uint32_t)(r * 128 + ((sc ^ (r & 7)) * 16));
        arow_ok[i] = (m0 + r) < NN;
    }

    int a_row[4];
    #pragma unroll
    for (int mt = 0; mt < 4; mt++) a_row[mt] = wm * 64 + mt * 16 + (lane & 15);
    int a_lc = lane >> 4;
    int b_row0 = wn * 32 + ((lane >> 4) << 3) + (lane & 7);
    int b_row1 = b_row0 + 16;
    int b_lc = (lane >> 3) & 1;

    auto issue = [&](int s, int buf) {
        int k0 = s * BK;
        uint32_t base = sb + buf * STAGE_B;
        #pragma unroll
        for (int i = 0; i < 4; i++) {
            const void* src = aSrc + (size_t)(m0 + sr + i * 32) * KIN + k0 + koff;
            cpasync16(base + st_off[i], src, arow_ok[i]);
        }
        #pragma unroll
        for (int i = 0; i < 4; i++) {
            const void* src = bSrc + (size_t)(n0 + sr + i * 32) * KIN + k0 + koff;
            cpasync16(base + 16384 + st_off[i], src, true);
        }
        asm volatile("cp.async.commit_group;" ::: "memory");
    };

    issue(0, 0);
    issue(1, 1);

    int cbuf = 0, nbuf = 2;
    #pragma unroll 1
    for (int kt = 0; kt < NKT; kt++) {
        if (kt < NKT - 1) asm volatile("cp.async.wait_group 1;" ::: "memory");
        else              asm volatile("cp.async.wait_group 0;" ::: "memory");
        __syncthreads();

        if (kt + 2 < NKT) {
            issue(kt + 2, nbuf);
        } else {
            asm volatile("cp.async.commit_group;" ::: "memory");
        }

        uint32_t ab = sb + cbuf * STAGE_B;
        uint32_t bb = ab + 16384;

        #pragma unroll
        for (int g = 0; g < 2; g++) {
            uint32_t bhf[8], blf[8];
            {
                int ch = g * 2 + b_lc;
                uint32_t o0h = (uint32_t)(b_row0 * 128 + ((ch ^ (b_row0 & 7)) * 16));
                uint32_t o1h = (uint32_t)(b_row1 * 128 + ((ch ^ (b_row1 & 7)) * 16));
                uint32_t o0l = (uint32_t)(b_row0 * 128 + (((ch + 4) ^ (b_row0 & 7)) * 16));
                uint32_t o1l = (uint32_t)(b_row1 * 128 + (((ch + 4) ^ (b_row1 & 7)) * 16));
                ldmx4(bhf[0], bhf[1], bhf[2], bhf[3], bb + o0h);
                ldmx4(bhf[4], bhf[5], bhf[6], bhf[7], bb + o1h);
                ldmx4(blf[0], blf[1], blf[2], blf[3], bb + o0l);
                ldmx4(blf[4], blf[5], blf[6], blf[7], bb + o1l);
            }
            #pragma unroll
            for (int mt = 0; mt < 4; mt++) {
                uint32_t ahf[4], alf[4];
                int r = a_row[mt];
                int ch = g * 2 + a_lc;
                uint32_t oh = (uint32_t)(r * 128 + ((ch ^ (r & 7)) * 16));
                uint32_t ol = (uint32_t)(r * 128 + (((ch + 4) ^ (r & 7)) * 16));
                ldmx4(ahf[0], ahf[1], ahf[2], ahf[3], ab + oh);
                ldmx4(alf[0], alf[1], alf[2], alf[3], ab + ol);
                #pragma unroll
                for (int nt = 0; nt < 4; nt++) {
                    mma16816(acc[mt][nt], ahf, &bhf[nt * 2]);
                    mma16816(acc[mt][nt], ahf, &blf[nt * 2]);
                    mma16816(acc[mt][nt], alf, &bhf[nt * 2]);
                }
            }
        }

        cbuf = (cbuf == 2) ? 0 : cbuf + 1;
        nbuf = (nbuf == 2) ? 0 : nbuf + 1;
    }

    int gid = lane >> 2, tig = lane & 3;
    if (n0 < 256) {
        // bases slab: store bf16x2
        #pragma unroll
        for (int mt = 0; mt < 4; mt++) {
            int row0 = m0 + wm * 64 + mt * 16 + gid;
            #pragma unroll
            for (int nt = 0; nt < 4; nt++) {
                int col = n0 + wn * 32 + nt * 8 + 2 * tig;
                __nv_bfloat162 p0 = __float22bfloat162_rn(make_float2(acc[mt][nt][0], acc[mt][nt][1]));
                __nv_bfloat162 p1 = __float22bfloat162_rn(make_float2(acc[mt][nt][2], acc[mt][nt][3]));
                if (row0 < NN)
                    *(uint32_t*)(g_bases_bf + (size_t)row0 * PB + col) = *(uint32_t*)&p0;
                if (row0 + 8 < NN)
                    *(uint32_t*)(g_bases_bf + (size_t)(row0 + 8) * PB + col) = *(uint32_t*)&p1;
            }
        }
    } else {
        int c0 = n0 - 256;
        #pragma unroll
        for (int mt = 0; mt < 4; mt++) {
            int row0 = m0 + wm * 64 + mt * 16 + gid;
            #pragma unroll
            for (int nt = 0; nt < 4; nt++) {
                int col = c0 + wn * 32 + nt * 8 + 2 * tig;
                if (row0 < NN)
                    *(float2*)(g_rest + (size_t)row0 * PR + col) = make_float2(acc[mt][nt][0], acc[mt][nt][1]);
                if (row0 + 8 < NN)
                    *(float2*)(g_rest + (size_t)(row0 + 8) * PR + col) = make_float2(acc[mt][nt][2], acc[mt][nt][3]);
            }
        }
    }
}

// ---------------- tail HMMA GEMM: orig cols [768,800) -> g_rest cols [512,544) ----------------
__global__ void __launch_bounds__(256, 2) k_gemm_tail(const float* __restrict__ x) {
    extern __shared__ char smem[];
    uint32_t sb = smem_u32(smem);
    int tid = threadIdx.x, wid = tid >> 5, lane = tid & 31;
    int m0 = blockIdx.x * BM;
    const int n0 = 768;
    int wm = wid & 1, wn = wid >> 1;

    float acc[4][4];
    #pragma unroll
    for (int i = 0; i < 4; i++)
        #pragma unroll
        for (int q = 0; q < 4; q++) acc[i][q] = 0.f;

    int sr = tid >> 3, sc = tid & 7;
    const bool arow_ok[4] = { (m0 + sr) < NN, (m0 + sr + 32) < NN,
                              (m0 + sr + 64) < NN, (m0 + sr + 96) < NN };
    uint32_t st_off[4];
    #pragma unroll
    for (int v = 0; v < 4; v++) {
        int r = sr + v * 32;
        st_off[v] = (uint32_t)(r * 128 + ((sc ^ (r & 7)) * 16));
    }
    uint32_t bst_off = (uint32_t)(sr * 128 + ((sc ^ (sr & 7)) * 16));

    int a_row[4];
    #pragma unroll
    for (int mt = 0; mt < 4; mt++) a_row[mt] = wm * 64 + mt * 16 + (lane & 15);
    int a_lc = lane >> 4;
    int b_rw = wn * 8 + (lane & 7);
    int b_ms = lane >> 3;

    {
        #pragma unroll
        for (int v = 0; v < 4; v++) {
            float f[8];
            if (arow_ok[v]) {
                const float* p = x + (size_t)(m0 + sr + v * 32) * KIN + sc * 8;
                *(float4*)&f[0] = *(const float4*)p;
                *(float4*)&f[4] = *(const float4*)(p + 4);
            } else {
                #pragma unroll
                for (int q = 0; q < 8; q++) f[q] = 0.f;
            }
            uint4 hi, lo; split8(f, hi, lo);
            *(uint4*)(smem + T_AH + st_off[v]) = hi;
            *(uint4*)(smem + T_AL + st_off[v]) = lo;
        }
        size_t off = (size_t)(n0 + sr) * KIN + sc * 8;
        *(uint4*)(smem + T_BH + bst_off) = *(const uint4*)(g_WhiT + off);
        *(uint4*)(smem + T_BL + bst_off) = *(const uint4*)(g_WloT + off);
    }
    __syncthreads();

    #pragma unroll 1
    for (int kt = 0; kt < KIN / 64; kt++) {
        int cur = kt & 1;
        bool more = (kt + 1) < (KIN / 64);

        float pa[4][8];
        uint4 pbh, pbl;
        if (more) {
            int k0 = (kt + 1) * 64;
            #pragma unroll
            for (int v = 0; v < 4; v++) {
                if (arow_ok[v]) {
                    const float* p = x + (size_t)(m0 + sr + v * 32) * KIN + k0 + sc * 8;
                    *(float4*)&pa[v][0] = *(const float4*)p;
                    *(float4*)&pa[v][4] = *(const float4*)(p + 4);
                } else {
                    #pragma unroll
                    for (int q = 0; q < 8; q++) pa[v][q] = 0.f;
                }
            }
            size_t off = (size_t)(n0 + sr) * KIN + k0 + sc * 8;
            pbh = *(const uint4*)(g_WhiT + off);
            pbl = *(const uint4*)(g_WloT + off);
        }

        uint32_t ah_b = sb + cur * T_STAGE + T_AH;
        uint32_t al_b = sb + cur * T_STAGE + T_AL;
        uint32_t bh_b = sb + cur * T_STAGE + T_BH;
        uint32_t bl_b = sb + cur * T_STAGE + T_BL;

        #pragma unroll
        for (int p = 0; p < 2; p++) {
            uint32_t bhf[4], blf[4];
            uint32_t boff = (uint32_t)(b_rw * 128 + (((4 * p + b_ms) ^ (b_rw & 7)) * 16));
            ldmx4(bhf[0], bhf[1], bhf[2], bhf[3], bh_b + boff);
            ldmx4(blf[0], blf[1], blf[2], blf[3], bl_b + boff);
            #pragma unroll
            for (int s = 0; s < 2; s++) {
                int k16 = 2 * p + s;
                uint32_t ahf[4][4], alf[4][4];
                #pragma unroll
                for (int mt = 0; mt < 4; mt++) {
                    int r = a_row[mt];
                    uint32_t off = (uint32_t)(r * 128 + (((k16 * 2 + a_lc) ^ (r & 7)) * 16));
                    ldmx4(ahf[mt][0], ahf[mt][1], ahf[mt][2], ahf[mt][3], ah_b + off);
                    ldmx4(alf[mt][0], alf[mt][1], alf[mt][2], alf[mt][3], al_b + off);
                }
                #pragma unroll
                for (int mt = 0; mt < 4; mt++) {
                    mma16816(acc[mt], ahf[mt], &bhf[2 * s]);
                    mma16816(acc[mt], ahf[mt], &blf[2 * s]);
                    mma16816(acc[mt], alf[mt], &bhf[2 * s]);
                }
            }
        }

        if (more) {
            char* dst = smem + (cur ^ 1) * T_STAGE;
            #pragma unroll
            for (int v = 0; v < 4; v++) {
                uint4 hi, lo; split8(pa[v], hi, lo);
                *(uint4*)(dst + T_AH + st_off[v]) = hi;
                *(uint4*)(dst + T_AL + st_off[v]) = lo;
            }
            *(uint4*)(dst + T_BH + bst_off) = pbh;
            *(uint4*)(dst + T_BL + bst_off) = pbl;
        }
        __syncthreads();
    }

    int gid = lane >> 2, tig = lane & 3;
    #pragma unroll
    for (int mt = 0; mt < 4; mt++) {
        int row0 = m0 + wm * 64 + mt * 16 + gid;
        int col = 512 + wn * 8 + 2 * tig;
        if (row0 < NN)
            *(float2*)(g_rest + (size_t)row0 * PR + col) = make_float2(acc[mt][0], acc[mt][1]);
        if (row0 + 8 < NN)
            *(float2*)(g_rest + (size_t)(row0 + 8) * PR + col) = make_float2(acc[mt][2], acc[mt][3]);
    }
}

// ---------------- fused gather (bf16 bases) + combine + residual + LN + ReLU (64 thr/node) ----------------
__global__ void __launch_bounds__(64) k_fused(
    const float* __restrict__ bcomb, const float* __restrict__ convb,
    const float* __restrict__ bres,  const float* __restrict__ gamma,
    const float* __restrict__ beta,  float* __restrict__ out)
{
    int n = blockIdx.x;
    int t = threadIdx.x;

    __shared__ float s_agg[4 * 65];
    __shared__ float s_w[32];
    __shared__ int   s_src[64];
    __shared__ float s_wt[64];
    __shared__ float s_red[4];

    float dn = g_dinv[n];
    const __nv_bfloat16* Bn = g_bases_bf + (size_t)n * PB;
    const float* Rn = g_rest + (size_t)n * PR;

    // self-loop: thread t owns bases cols [4t, 4t+4), bf16 -> fp32 accumulate
    float4 acc;
    {
        uint2 u = *(const uint2*)(Bn + 4 * t);
        float2 f0 = __bfloat1622float2(*(__nv_bfloat162*)&u.x);
        float2 f1 = __bfloat1622float2(*(__nv_bfloat162*)&u.y);
        float dn2 = dn * dn;
        acc.x = f0.x * dn2; acc.y = f0.y * dn2;
        acc.z = f1.x * dn2; acc.w = f1.y * dn2;
    }

    int start = g_rowstart[n];
    int end   = g_rowstart[n + 1];
    for (int base = start; base < end; base += 64) {
        int cnt = min(64, end - base);
        if (t < cnt) {
            int s = g_csr[base + t];
            s_src[t] = s;
            s_wt[t]  = g_dinv[s] * dn;
        }
        __syncthreads();
        int j = 0;
        for (; j + 4 <= cnt; j += 4) {
            uint2 u0 = *(const uint2*)(g_bases_bf + (size_t)s_src[j]     * PB + 4 * t);
            uint2 u1 = *(const uint2*)(g_bases_bf + (size_t)s_src[j + 1] * PB + 4 * t);
            uint2 u2 = *(const uint2*)(g_bases_bf + (size_t)s_src[j + 2] * PB + 4 * t);
            uint2 u3 = *(const uint2*)(g_bases_bf + (size_t)s_src[j + 3] * PB + 4 * t);
            float w0 = s_wt[j], w1 = s_wt[j + 1], w2 = s_wt[j + 2], w3 = s_wt[j + 3];
            float2 a, b;
            a = __bfloat1622float2(*(__nv_bfloat162*)&u0.x);
            b = __bfloat1622float2(*(__nv_bfloat162*)&u0.y);
            acc.x = fmaf(a.x, w0, acc.x); acc.y = fmaf(a.y, w0, acc.y);
            acc.z = fmaf(b.x, w0, acc.z); acc.w = fmaf(b.y, w0, acc.w);
            a = __bfloat1622float2(*(__nv_bfloat162*)&u1.x);
            b = __bfloat1622float2(*(__nv_bfloat162*)&u1.y);
            acc.x = fmaf(a.x, w1, acc.x); acc.y = fmaf(a.y, w1, acc.y);
            acc.z = fmaf(b.x, w1, acc.z); acc.w = fmaf(b.y, w1, acc.w);
            a = __bfloat1622float2(*(__nv_bfloat162*)&u2.x);
            b = __bfloat1622float2(*(__nv_bfloat162*)&u2.y);
            acc.x = fmaf(a.x, w2, acc.x); acc.y = fmaf(a.y, w2, acc.y);
            acc.z = fmaf(b.x, w2, acc.z); acc.w = fmaf(b.y, w2, acc.w);
            a = __bfloat1622float2(*(__nv_bfloat162*)&u3.x);
            b = __bfloat1622float2(*(__nv_bfloat162*)&u3.y);
            acc.x = fmaf(a.x, w3, acc.x); acc.y = fmaf(a.y, w3, acc.y);
            acc.z = fmaf(b.x, w3, acc.z); acc.w = fmaf(b.y, w3, acc.w);
        }
        for (; j < cnt; j++) {
            uint2 u = *(const uint2*)(g_bases_bf + (size_t)s_src[j] * PB + 4 * t);
            float w = s_wt[j];
            float2 a = __bfloat1622float2(*(__nv_bfloat162*)&u.x);
            float2 b = __bfloat1622float2(*(__nv_bfloat162*)&u.y);
            acc.x = fmaf(a.x, w, acc.x); acc.y = fmaf(a.y, w, acc.y);
            acc.z = fmaf(b.x, w, acc.z); acc.w = fmaf(b.y, w, acc.w);
        }
        __syncthreads();
    }

    {
        int c0 = t * 4, b = c0 >> 6, f = c0 & 63;
        float* p = &s_agg[b * 65 + f];
        p[0] = acc.x; p[1] = acc.y; p[2] = acc.z; p[3] = acc.w;
    }
    if (t < 32) s_w[t] = Rn[t] + bcomb[t];
    __syncthreads();

    int o0 = t * 8;
    int h  = t >> 3;
    int f0 = (t & 7) * 8;
    float w0 = s_w[h * 4 + 0], w1 = s_w[h * 4 + 1];
    float w2 = s_w[h * 4 + 2], w3 = s_w[h * 4 + 3];

    float res[8], cbv[8], brv[8];
    *(float4*)&res[0] = *(const float4*)(Rn + 32 + o0);
    *(float4*)&res[4] = *(const float4*)(Rn + 32 + o0 + 4);
    *(float4*)&cbv[0] = *(const float4*)(convb + o0);
    *(float4*)&cbv[4] = *(const float4*)(convb + o0 + 4);
    *(float4*)&brv[0] = *(const float4*)(bres + o0);
    *(float4*)&brv[4] = *(const float4*)(bres + o0 + 4);

    float v[8];
    float sum = 0.f, sq = 0.f;
    #pragma unroll
    for (int j = 0; j < 8; j++) {
        int f = f0 + j;
        float c = w0 * s_agg[f] + w1 * s_agg[65 + f] + w2 * s_agg[130 + f] + w3 * s_agg[195 + f];
        c += cbv[j] + res[j] + brv[j];
        v[j] = c;
        sum += c;
        sq = fmaf(c, c, sq);
    }

    #pragma unroll
    for (int off = 16; off; off >>= 1) {
        sum += __shfl_xor_sync(0xffffffffu, sum, off);
        sq  += __shfl_xor_sync(0xffffffffu, sq, off);
    }
    if ((t & 31) == 0) { s_red[t >> 5] = sum; s_red[2 + (t >> 5)] = sq; }
    __syncthreads();
    sum = s_red[0] + s_red[1];
    sq  = s_red[2] + s_red[3];

    float mean = sum * (1.0f / 512.0f);
    float var  = sq * (1.0f / 512.0f) - mean * mean;
    float rstd = rsqrtf(var + 1e-5f);

    float gm[8], bt[8], o[8];
    *(float4*)&gm[0] = *(const float4*)(gamma + o0);
    *(float4*)&gm[4] = *(const float4*)(gamma + o0 + 4);
    *(float4*)&bt[0] = *(const float4*)(beta + o0);
    *(float4*)&bt[4] = *(const float4*)(beta + o0 + 4);
    #pragma unroll
    for (int j = 0; j < 8; j++)
        o[j] = fmaxf(0.f, (v[j] - mean) * rstd * gm[j] + bt[j]);
    float* op = out + (size_t)n * 512 + o0;
    *(float4*)op       = *(float4*)&o[0];
    *(float4*)(op + 4) = *(float4*)&o[4];
}

// ---------------- launch (round-8 fork/join, graph-capturable) ----------------
extern "C" void kernel_launch(void* const* d_in, const int* in_sizes, int n_in,
                              void* d_out, int out_size) {
    const float* x  = (const float*)d_in[0];
    const int*   ei = (const int*)d_in[1];
    const float* Wb = (const float*)d_in[2];
    const float* Wc = (const float*)d_in[3];
    const float* bc = (const float*)d_in[4];
    const float* cb = (const float*)d_in[5];
    const float* Wr = (const float*)d_in[6];
    const float* br = (const float*)d_in[7];
    const float* gm = (const float*)d_in[8];
    const float* bt = (const float*)d_in[9];
    float* out = (float*)d_out;

    static cudaStream_t s1 = nullptr, s2 = nullptr;
    static cudaEvent_t  ev0 = nullptr, evP = nullptr, ev1 = nullptr, ev2 = nullptr;
    static bool init = false;
    if (!init) {
        cudaStreamCreateWithFlags(&s1, cudaStreamNonBlocking);
        cudaStreamCreateWithFlags(&s2, cudaStreamNonBlocking);
        cudaEventCreateWithFlags(&ev0, cudaEventDisableTiming);
        cudaEventCreateWithFlags(&evP, cudaEventDisableTiming);
        cudaEventCreateWithFlags(&ev1, cudaEventDisableTiming);
        cudaEventCreateWithFlags(&ev2, cudaEventDisableTiming);
        cudaFuncSetAttribute(k_gemm_mma,  cudaFuncAttributeMaxDynamicSharedMemorySize, GEMM_SMEM);
        cudaFuncSetAttribute(k_gemm_tail, cudaFuncAttributeMaxDynamicSharedMemorySize, TAIL_SMEM);
        init = true;
    }

    // fork: s1 = packT -> tail, s2 = prep chain
    cudaEventRecord(ev0, 0);
    cudaStreamWaitEvent(s1, ev0, 0);
    cudaStreamWaitEvent(s2, ev0, 0);

    k_packT<<<(800 * KIN + 255) / 256, 256, 0, s1>>>(Wb, Wc, Wr);           // idx 0
    cudaEventRecord(evP, s1);

    k_split<<<(NN * KIN / 4 + 255) / 256, 256>>>(x);                        // idx 1 (main)
    k_gemm_tail<<<(NN + BM - 1) / BM, 256, TAIL_SMEM, s1>>>(x);             // idx 2 (s1)

    cudaStreamWaitEvent(0, evP, 0);
    dim3 gg(NTILES_N, (NN + BM - 1) / BM);
    k_gemm_mma<<<gg, 256, GEMM_SMEM>>>();                                   // idx 3 (main, profiled)

    k_zero<<<(NN + 255) / 256, 256, 0, s2>>>();                             // idx 4
    k_hist<<<(EE + 255) / 256, 256, 0, s2>>>(ei);                           // idx 5
    k_dinv<<<(NN + 255) / 256, 256, 0, s2>>>();                             // idx 6
    k_scan1<<<NBLK, 1024, 0, s2>>>();                                       // idx 7
    k_scan2<<<1, 64, 0, s2>>>();                                            // idx 8
    k_scan3<<<NBLK, 1024, 0, s2>>>();                                       // idx 9
    k_fill<<<(EE + 255) / 256, 256, 0, s2>>>(ei);                           // idx 10

    // join
    cudaEventRecord(ev1, s1);
    cudaEventRecord(ev2, s2);
    cudaStreamWaitEvent(0, ev1, 0);
    cudaStreamWaitEvent(0, ev2, 0);

    k_fused<<<NN, 64>>>(bc, cb, br, gm, bt, out);                           // idx 11
}

// round 12
// speedup vs baseline: 1.0650x; 1.0092x over previous
#include <cuda_runtime.h>
#include <cuda_bf16.h>
#include <cuda_fp16.h>
#include <cstdint>

#define NN   50000
#define EE   800000
#define KIN  512
#define NBLK 49

#define PB 256              // bases cols (fp16 slab)
#define PR 544              // rest: [0,32) comb | [32,544) res (fp32)

#define BM 128
#define BN 128
#define BK 32
#define NKT (KIN / BK)
#define NTILES_N 6
#define STAGE_B 32768
#define GEMM_SMEM (3 * STAGE_B)

#define T_AH 0
#define T_AL 16384
#define T_BH 32768
#define T_BL 36864
#define T_STAGE 40960
#define TAIL_SMEM (2 * T_STAGE)

// ---------------- static device scratch ----------------
__device__ __half g_bases_h[(size_t)NN * PB];           // 25.6 MB fp16 gather slab
__device__ float g_rest[(size_t)NN * PR];
__device__ __nv_bfloat16 g_xhi[(size_t)NN * KIN];
__device__ __nv_bfloat16 g_xlo[(size_t)NN * KIN];
__device__ __nv_bfloat16 g_WhiT[(size_t)800 * KIN];
__device__ __nv_bfloat16 g_WloT[(size_t)800 * KIN];
__device__ float g_dinv[NN];
__device__ int   g_hist[NN];
__device__ int   g_rowstart[NN + 1];
__device__ int   g_cursor[NN];
__device__ int   g_csr[EE];
__device__ int   g_part[64];

// ---------------- helpers ----------------
__device__ __forceinline__ uint32_t smem_u32(const void* p) {
    uint32_t a;
    asm("{ .reg .u64 t; cvta.to.shared.u64 t, %1; cvt.u32.u64 %0, t; }" : "=r"(a) : "l"(p));
    return a;
}
__device__ __forceinline__ void ldmx4(uint32_t& r0, uint32_t& r1, uint32_t& r2, uint32_t& r3, uint32_t addr) {
    asm volatile("ldmatrix.sync.aligned.m8n8.x4.shared.b16 {%0,%1,%2,%3}, [%4];"
                 : "=r"(r0), "=r"(r1), "=r"(r2), "=r"(r3) : "r"(addr));
}
__device__ __forceinline__ void mma16816(float* c, const uint32_t* a, const uint32_t* b) {
    asm volatile(
        "mma.sync.aligned.m16n8k16.row.col.f32.bf16.bf16.f32 "
        "{%0,%1,%2,%3}, {%4,%5,%6,%7}, {%8,%9}, {%0,%1,%2,%3};"
        : "+f"(c[0]), "+f"(c[1]), "+f"(c[2]), "+f"(c[3])
        : "r"(a[0]), "r"(a[1]), "r"(a[2]), "r"(a[3]), "r"(b[0]), "r"(b[1]));
}
__device__ __forceinline__ void cpasync16(uint32_t dst, const void* src, bool pred) {
    int sz = pred ? 16 : 0;
    asm volatile("cp.async.cg.shared.global [%0], [%1], 16, %2;"
                 :: "r"(dst), "l"(src), "r"(sz) : "memory");
}
__device__ __forceinline__ void split8(const float* f, uint4& hi, uint4& lo) {
    uint32_t h[4], l[4];
    #pragma unroll
    for (int i = 0; i < 4; i++) {
        __nv_bfloat162 h2 = __float22bfloat162_rn(make_float2(f[2 * i], f[2 * i + 1]));
        float r0 = f[2 * i]     - __bfloat162float(__low2bfloat16(h2));
        float r1 = f[2 * i + 1] - __bfloat162float(__high2bfloat16(h2));
        __nv_bfloat162 l2 = __float22bfloat162_rn(make_float2(r0, r1));
        h[i] = *(uint32_t*)&h2;
        l[i] = *(uint32_t*)&l2;
    }
    hi = make_uint4(h[0], h[1], h[2], h[3]);
    lo = make_uint4(l[0], l[1], l[2], l[3]);
}

// ---------------- graph prep ----------------
__global__ void k_zero() {
    int i = blockIdx.x * blockDim.x + threadIdx.x;
    if (i < NN) { g_hist[i] = 0; g_cursor[i] = 0; }
}
__global__ void k_hist(const int* __restrict__ ei) {
    int e = blockIdx.x * blockDim.x + threadIdx.x;
    if (e < EE) atomicAdd(&g_hist[ei[EE + e]], 1);
}
__global__ void k_dinv() {
    int i = blockIdx.x * blockDim.x + threadIdx.x;
    if (i < NN) g_dinv[i] = rsqrtf((float)(g_hist[i] + 1));
}
__global__ void k_scan1() {
    __shared__ int s[1024];
    int b = blockIdx.x, t = threadIdx.x, i = b * 1024 + t;
    int v = (i < NN) ? g_hist[i] : 0;
    int x = v; s[t] = x; __syncthreads();
    #pragma unroll
    for (int off = 1; off < 1024; off <<= 1) {
        int tmp = (t >= off) ? s[t - off] : 0;
        __syncthreads();
        x += tmp; s[t] = x;
        __syncthreads();
    }
    if (i < NN) g_rowstart[i] = x - v;
    if (t == 1023) g_part[b] = x;
}
__global__ void k_scan2() {
    __shared__ int s[64];
    int t = threadIdx.x;
    int v = (t < NBLK) ? g_part[t] : 0;
    int x = v; s[t] = x; __syncthreads();
    #pragma unroll
    for (int off = 1; off < 64; off <<= 1) {
        int tmp = (t >= off) ? s[t - off] : 0;
        __syncthreads();
        x += tmp; s[t] = x;
        __syncthreads();
    }
    if (t < NBLK) g_part[t] = x - v;
    if (t == 63) g_rowstart[NN] = s[63];
}
__global__ void k_scan3() {
    int b = blockIdx.x, i = b * 1024 + threadIdx.x;
    if (i < NN) g_rowstart[i] += g_part[b];
}
__global__ void k_fill(const int* __restrict__ ei) {
    int e = blockIdx.x * blockDim.x + threadIdx.x;
    if (e < EE) {
        int d = ei[EE + e];
        int p = atomicAdd(&g_cursor[d], 1);
        g_csr[g_rowstart[d] + p] = ei[e];
    }
}
__global__ void k_packT(const float* __restrict__ Wb, const float* __restrict__ Wc,
                        const float* __restrict__ Wr) {
    int idx = blockIdx.x * blockDim.x + threadIdx.x;
    if (idx >= 800 * KIN) return;
    int n = idx / KIN, k = idx % KIN;
    float v;
    if (n < 256)      v = Wb[k * 256 + n];
    else if (n < 288) v = Wc[k * 32 + (n - 256)];
    else              v = Wr[k * 512 + (n - 288)];
    __nv_bfloat16 h = __float2bfloat16(v);
    g_WhiT[idx] = h;
    g_WloT[idx] = __float2bfloat16(v - __bfloat162float(h));
}
__global__ void k_split(const float* __restrict__ x) {
    size_t i = (size_t)blockIdx.x * blockDim.x + threadIdx.x;
    if (i >= (size_t)NN * KIN / 4) return;
    float4 v = ((const float4*)x)[i];
    float f[4] = {v.x, v.y, v.z, v.w};
    uint32_t h[2], l[2];
    #pragma unroll
    for (int q = 0; q < 2; q++) {
        __nv_bfloat162 h2 = __float22bfloat162_rn(make_float2(f[2 * q], f[2 * q + 1]));
        float r0 = f[2 * q]     - __bfloat162float(__low2bfloat16(h2));
        float r1 = f[2 * q + 1] - __bfloat162float(__high2bfloat16(h2));
        __nv_bfloat162 l2 = __float22bfloat162_rn(make_float2(r0, r1));
        h[q] = *(uint32_t*)&h2;
        l[q] = *(uint32_t*)&l2;
    }
    ((uint2*)g_xhi)[i] = make_uint2(h[0], h[1]);
    ((uint2*)g_xlo)[i] = make_uint2(l[0], l[1]);
}

// ---------------- main HMMA GEMM (round-8 wave version): cols [0,768) ----------------
// cols [0,256) -> g_bases_h (fp16), cols [256,768) -> g_rest[0,512) (fp32)
__global__ void __launch_bounds__(256, 2) k_gemm_mma() {
    extern __shared__ char smem[];
    uint32_t sb = smem_u32(smem);
    int tid = threadIdx.x, wid = tid >> 5, lane = tid & 31;
    int m0 = blockIdx.y * BM, n0 = blockIdx.x * BN;
    int wm = wid & 1, wn = wid >> 1;

    float acc[4][4][4];
    #pragma unroll
    for (int i = 0; i < 4; i++)
        #pragma unroll
        for (int j = 0; j < 4; j++)
            #pragma unroll
            for (int q = 0; q < 4; q++) acc[i][j][q] = 0.f;

    int sr = tid >> 3, sc = tid & 7;
    const __nv_bfloat16* aSrc = (sc < 4) ? g_xhi : g_xlo;
    const __nv_bfloat16* bSrc = (sc < 4) ? g_WhiT : g_WloT;
    int koff = (sc & 3) * 8;
    uint32_t st_off[4];
    bool arow_ok[4];
    #pragma unroll
    for (int i = 0; i < 4; i++) {
        int r = sr + i * 32;
        st_off[i] = (uint32_t)(r * 128 + ((sc ^ (r & 7)) * 16));
        arow_ok[i] = (m0 + r) < NN;
    }

    int a_row[4];
    #pragma unroll
    for (int mt = 0; mt < 4; mt++) a_row[mt] = wm * 64 + mt * 16 + (lane & 15);
    int a_lc = lane >> 4;
    int b_row0 = wn * 32 + ((lane >> 4) << 3) + (lane & 7);
    int b_row1 = b_row0 + 16;
    int b_lc = (lane >> 3) & 1;

    auto issue = [&](int s, int buf) {
        int k0 = s * BK;
        uint32_t base = sb + buf * STAGE_B;
        #pragma unroll
        for (int i = 0; i < 4; i++) {
            const void* src = aSrc + (size_t)(m0 + sr + i * 32) * KIN + k0 + koff;
            cpasync16(base + st_off[i], src, arow_ok[i]);
        }
        #pragma unroll
        for (int i = 0; i < 4; i++) {
            const void* src = bSrc + (size_t)(n0 + sr + i * 32) * KIN + k0 + koff;
            cpasync16(base + 16384 + st_off[i], src, true);
        }
        asm volatile("cp.async.commit_group;" ::: "memory");
    };

    issue(0, 0);
    issue(1, 1);

    int cbuf = 0, nbuf = 2;
    #pragma unroll 1
    for (int kt = 0; kt < NKT; kt++) {
        if (kt < NKT - 1) asm volatile("cp.async.wait_group 1;" ::: "memory");
        else              asm volatile("cp.async.wait_group 0;" ::: "memory");
        __syncthreads();

        if (kt + 2 < NKT) {
            issue(kt + 2, nbuf);
        } else {
            asm volatile("cp.async.commit_group;" ::: "memory");
        }

        uint32_t ab = sb + cbuf * STAGE_B;
        uint32_t bb = ab + 16384;

        #pragma unroll
        for (int g = 0; g < 2; g++) {
            uint32_t bhf[8], blf[8];
            {
                int ch = g * 2 + b_lc;
                uint32_t o0h = (uint32_t)(b_row0 * 128 + ((ch ^ (b_row0 & 7)) * 16));
                uint32_t o1h = (uint32_t)(b_row1 * 128 + ((ch ^ (b_row1 & 7)) * 16));
                uint32_t o0l = (uint32_t)(b_row0 * 128 + (((ch + 4) ^ (b_row0 & 7)) * 16));
                uint32_t o1l = (uint32_t)(b_row1 * 128 + (((ch + 4) ^ (b_row1 & 7)) * 16));
                ldmx4(bhf[0], bhf[1], bhf[2], bhf[3], bb + o0h);
                ldmx4(bhf[4], bhf[5], bhf[6], bhf[7], bb + o1h);
                ldmx4(blf[0], blf[1], blf[2], blf[3], bb + o0l);
                ldmx4(blf[4], blf[5], blf[6], blf[7], bb + o1l);
            }
            #pragma unroll
            for (int mt = 0; mt < 4; mt++) {
                uint32_t ahf[4], alf[4];
                int r = a_row[mt];
                int ch = g * 2 + a_lc;
                uint32_t oh = (uint32_t)(r * 128 + ((ch ^ (r & 7)) * 16));
                uint32_t ol = (uint32_t)(r * 128 + (((ch + 4) ^ (r & 7)) * 16));
                ldmx4(ahf[0], ahf[1], ahf[2], ahf[3], ab + oh);
                ldmx4(alf[0], alf[1], alf[2], alf[3], ab + ol);
                #pragma unroll
                for (int nt = 0; nt < 4; nt++) {
                    mma16816(acc[mt][nt], ahf, &bhf[nt * 2]);
                    mma16816(acc[mt][nt], ahf, &blf[nt * 2]);
                    mma16816(acc[mt][nt], alf, &bhf[nt * 2]);
                }
            }
        }

        cbuf = (cbuf == 2) ? 0 : cbuf + 1;
        nbuf = (nbuf == 2) ? 0 : nbuf + 1;
    }

    int gid = lane >> 2, tig = lane & 3;
    if (n0 < 256) {
        // bases slab: store fp16x2
        #pragma unroll
        for (int mt = 0; mt < 4; mt++) {
            int row0 = m0 + wm * 64 + mt * 16 + gid;
            #pragma unroll
            for (int nt = 0; nt < 4; nt++) {
                int col = n0 + wn * 32 + nt * 8 + 2 * tig;
                __half2 p0 = __float22half2_rn(make_float2(acc[mt][nt][0], acc[mt][nt][1]));
                __half2 p1 = __float22half2_rn(make_float2(acc[mt][nt][2], acc[mt][nt][3]));
                if (row0 < NN)
                    *(uint32_t*)(g_bases_h + (size_t)row0 * PB + col) = *(uint32_t*)&p0;
                if (row0 + 8 < NN)
                    *(uint32_t*)(g_bases_h + (size_t)(row0 + 8) * PB + col) = *(uint32_t*)&p1;
            }
        }
    } else {
        int c0 = n0 - 256;
        #pragma unroll
        for (int mt = 0; mt < 4; mt++) {
            int row0 = m0 + wm * 64 + mt * 16 + gid;
            #pragma unroll
            for (int nt = 0; nt < 4; nt++) {
                int col = c0 + wn * 32 + nt * 8 + 2 * tig;
                if (row0 < NN)
                    *(float2*)(g_rest + (size_t)row0 * PR + col) = make_float2(acc[mt][nt][0], acc[mt][nt][1]);
                if (row0 + 8 < NN)
                    *(float2*)(g_rest + (size_t)(row0 + 8) * PR + col) = make_float2(acc[mt][nt][2], acc[mt][nt][3]);
            }
        }
    }
}

// ---------------- tail HMMA GEMM: orig cols [768,800) -> g_rest cols [512,544) ----------------
__global__ void __launch_bounds__(256, 2) k_gemm_tail(const float* __restrict__ x) {
    extern __shared__ char smem[];
    uint32_t sb = smem_u32(smem);
    int tid = threadIdx.x, wid = tid >> 5, lane = tid & 31;
    int m0 = blockIdx.x * BM;
    const int n0 = 768;
    int wm = wid & 1, wn = wid >> 1;

    float acc[4][4];
    #pragma unroll
    for (int i = 0; i < 4; i++)
        #pragma unroll
        for (int q = 0; q < 4; q++) acc[i][q] = 0.f;

    int sr = tid >> 3, sc = tid & 7;
    const bool arow_ok[4] = { (m0 + sr) < NN, (m0 + sr + 32) < NN,
                              (m0 + sr + 64) < NN, (m0 + sr + 96) < NN };
    uint32_t st_off[4];
    #pragma unroll
    for (int v = 0; v < 4; v++) {
        int r = sr + v * 32;
        st_off[v] = (uint32_t)(r * 128 + ((sc ^ (r & 7)) * 16));
    }
    uint32_t bst_off = (uint32_t)(sr * 128 + ((sc ^ (sr & 7)) * 16));

    int a_row[4];
    #pragma unroll
    for (int mt = 0; mt < 4; mt++) a_row[mt] = wm * 64 + mt * 16 + (lane & 15);
    int a_lc = lane >> 4;
    int b_rw = wn * 8 + (lane & 7);
    int b_ms = lane >> 3;

    {
        #pragma unroll
        for (int v = 0; v < 4; v++) {
            float f[8];
            if (arow_ok[v]) {
                const float* p = x + (size_t)(m0 + sr + v * 32) * KIN + sc * 8;
                *(float4*)&f[0] = *(const float4*)p;
                *(float4*)&f[4] = *(const float4*)(p + 4);
            } else {
                #pragma unroll
                for (int q = 0; q < 8; q++) f[q] = 0.f;
            }
            uint4 hi, lo; split8(f, hi, lo);
            *(uint4*)(smem + T_AH + st_off[v]) = hi;
            *(uint4*)(smem + T_AL + st_off[v]) = lo;
        }
        size_t off = (size_t)(n0 + sr) * KIN + sc * 8;
        *(uint4*)(smem + T_BH + bst_off) = *(const uint4*)(g_WhiT + off);
        *(uint4*)(smem + T_BL + bst_off) = *(const uint4*)(g_WloT + off);
    }
    __syncthreads();

    #pragma unroll 1
    for (int kt = 0; kt < KIN / 64; kt++) {
        int cur = kt & 1;
        bool more = (kt + 1) < (KIN / 64);

        float pa[4][8];
        uint4 pbh, pbl;
        if (more) {
            int k0 = (kt + 1) * 64;
            #pragma unroll
            for (int v = 0; v < 4; v++) {
                if (arow_ok[v]) {
                    const float* p = x + (size_t)(m0 + sr + v * 32) * KIN + k0 + sc * 8;
                    *(float4*)&pa[v][0] = *(const float4*)p;
                    *(float4*)&pa[v][4] = *(const float4*)(p + 4);
                } else {
                    #pragma unroll
                    for (int q = 0; q < 8; q++) pa[v][q] = 0.f;
                }
            }
            size_t off = (size_t)(n0 + sr) * KIN + k0 + sc * 8;
            pbh = *(const uint4*)(g_WhiT + off);
            pbl = *(const uint4*)(g_WloT + off);
        }

        uint32_t ah_b = sb + cur * T_STAGE + T_AH;
        uint32_t al_b = sb + cur * T_STAGE + T_AL;
        uint32_t bh_b = sb + cur * T_STAGE + T_BH;
        uint32_t bl_b = sb + cur * T_STAGE + T_BL;

        #pragma unroll
        for (int p = 0; p < 2; p++) {
            uint32_t bhf[4], blf[4];
            uint32_t boff = (uint32_t)(b_rw * 128 + (((4 * p + b_ms) ^ (b_rw & 7)) * 16));
            ldmx4(bhf[0], bhf[1], bhf[2], bhf[3], bh_b + boff);
            ldmx4(blf[0], blf[1], blf[2], blf[3], bl_b + boff);
            #pragma unroll
            for (int s = 0; s < 2; s++) {
                int k16 = 2 * p + s;
                uint32_t ahf[4][4], alf[4][4];
                #pragma unroll
                for (int mt = 0; mt < 4; mt++) {
                    int r = a_row[mt];
                    uint32_t off = (uint32_t)(r * 128 + (((k16 * 2 + a_lc) ^ (r & 7)) * 16));
                    ldmx4(ahf[mt][0], ahf[mt][1], ahf[mt][2], ahf[mt][3], ah_b + off);
                    ldmx4(alf[mt][0], alf[mt][1], alf[mt][2], alf[mt][3], al_b + off);
                }
                #pragma unroll
                for (int mt = 0; mt < 4; mt++) {
                    mma16816(acc[mt], ahf[mt], &bhf[2 * s]);
                    mma16816(acc[mt], ahf[mt], &blf[2 * s]);
                    mma16816(acc[mt], alf[mt], &bhf[2 * s]);
                }
            }
        }

        if (more) {
            char* dst = smem + (cur ^ 1) * T_STAGE;
            #pragma unroll
            for (int v = 0; v < 4; v++) {
                uint4 hi, lo; split8(pa[v], hi, lo);
                *(uint4*)(dst + T_AH + st_off[v]) = hi;
                *(uint4*)(dst + T_AL + st_off[v]) = lo;
            }
            *(uint4*)(dst + T_BH + bst_off) = pbh;
            *(uint4*)(dst + T_BL + bst_off) = pbl;
        }
        __syncthreads();
    }

    int gid = lane >> 2, tig = lane & 3;
    #pragma unroll
    for (int mt = 0; mt < 4; mt++) {
        int row0 = m0 + wm * 64 + mt * 16 + gid;
        int col = 512 + wn * 8 + 2 * tig;
        if (row0 < NN)
            *(float2*)(g_rest + (size_t)row0 * PR + col) = make_float2(acc[mt][0], acc[mt][1]);
        if (row0 + 8 < NN)
            *(float2*)(g_rest + (size_t)(row0 + 8) * PR + col) = make_float2(acc[mt][2], acc[mt][3]);
    }
}

// ---------------- fused gather (fp16 bases) + combine + residual + LN + ReLU (64 thr/node) ----------------
__global__ void __launch_bounds__(64) k_fused(
    const float* __restrict__ bcomb, const float* __restrict__ convb,
    const float* __restrict__ bres,  const float* __restrict__ gamma,
    const float* __restrict__ beta,  float* __restrict__ out)
{
    int n = blockIdx.x;
    int t = threadIdx.x;

    __shared__ float s_agg[4 * 65];
    __shared__ float s_w[32];
    __shared__ int   s_src[64];
    __shared__ float s_wt[64];
    __shared__ float s_red[4];

    float dn = g_dinv[n];
    const __half* Bn = g_bases_h + (size_t)n * PB;
    const float* Rn = g_rest + (size_t)n * PR;

    // self-loop: thread t owns bases cols [4t, 4t+4), fp16 -> fp32 accumulate
    float4 acc;
    {
        uint2 u = *(const uint2*)(Bn + 4 * t);
        float2 f0 = __half22float2(*(__half2*)&u.x);
        float2 f1 = __half22float2(*(__half2*)&u.y);
        float dn2 = dn * dn;
        acc.x = f0.x * dn2; acc.y = f0.y * dn2;
        acc.z = f1.x * dn2; acc.w = f1.y * dn2;
    }

    int start = g_rowstart[n];
    int end   = g_rowstart[n + 1];
    for (int base = start; base < end; base += 64) {
        int cnt = min(64, end - base);
        if (t < cnt) {
            int s = g_csr[base + t];
            s_src[t] = s;
            s_wt[t]  = g_dinv[s] * dn;
        }
        __syncthreads();
        int j = 0;
        for (; j + 4 <= cnt; j += 4) {
            uint2 u0 = *(const uint2*)(g_bases_h + (size_t)s_src[j]     * PB + 4 * t);
            uint2 u1 = *(const uint2*)(g_bases_h + (size_t)s_src[j + 1] * PB + 4 * t);
            uint2 u2 = *(const uint2*)(g_bases_h + (size_t)s_src[j + 2] * PB + 4 * t);
            uint2 u3 = *(const uint2*)(g_bases_h + (size_t)s_src[j + 3] * PB + 4 * t);
            float w0 = s_wt[j], w1 = s_wt[j + 1], w2 = s_wt[j + 2], w3 = s_wt[j + 3];
            float2 a, b;
            a = __half22float2(*(__half2*)&u0.x);
            b = __half22float2(*(__half2*)&u0.y);
            acc.x = fmaf(a.x, w0, acc.x); acc.y = fmaf(a.y, w0, acc.y);
            acc.z = fmaf(b.x, w0, acc.z); acc.w = fmaf(b.y, w0, acc.w);
            a = __half22float2(*(__half2*)&u1.x);
            b = __half22float2(*(__half2*)&u1.y);
            acc.x = fmaf(a.x, w1, acc.x); acc.y = fmaf(a.y, w1, acc.y);
            acc.z = fmaf(b.x, w1, acc.z); acc.w = fmaf(b.y, w1, acc.w);
            a = __half22float2(*(__half2*)&u2.x);
            b = __half22float2(*(__half2*)&u2.y);
            acc.x = fmaf(a.x, w2, acc.x); acc.y = fmaf(a.y, w2, acc.y);
            acc.z = fmaf(b.x, w2, acc.z); acc.w = fmaf(b.y, w2, acc.w);
            a = __half22float2(*(__half2*)&u3.x);
            b = __half22float2(*(__half2*)&u3.y);
            acc.x = fmaf(a.x, w3, acc.x); acc.y = fmaf(a.y, w3, acc.y);
            acc.z = fmaf(b.x, w3, acc.z); acc.w = fmaf(b.y, w3, acc.w);
        }
        for (; j < cnt; j++) {
            uint2 u = *(const uint2*)(g_bases_h + (size_t)s_src[j] * PB + 4 * t);
            float w = s_wt[j];
            float2 a = __half22float2(*(__half2*)&u.x);
            float2 b = __half22float2(*(__half2*)&u.y);
            acc.x = fmaf(a.x, w, acc.x); acc.y = fmaf(a.y, w, acc.y);
            acc.z = fmaf(b.x, w, acc.z); acc.w = fmaf(b.y, w, acc.w);
        }
        __syncthreads();
    }

    {
        int c0 = t * 4, b = c0 >> 6, f = c0 & 63;
        float* p = &s_agg[b * 65 + f];
        p[0] = acc.x; p[1] = acc.y; p[2] = acc.z; p[3] = acc.w;
    }
    if (t < 32) s_w[t] = Rn[t] + bcomb[t];
    __syncthreads();

    int o0 = t * 8;
    int h  = t >> 3;
    int f0 = (t & 7) * 8;
    float w0 = s_w[h * 4 + 0], w1 = s_w[h * 4 + 1];
    float w2 = s_w[h * 4 + 2], w3 = s_w[h * 4 + 3];

    float res[8], cbv[8], brv[8];
    *(float4*)&res[0] = *(const float4*)(Rn + 32 + o0);
    *(float4*)&res[4] = *(const float4*)(Rn + 32 + o0 + 4);
    *(float4*)&cbv[0] = *(const float4*)(convb + o0);
    *(float4*)&cbv[4] = *(const float4*)(convb + o0 + 4);
    *(float4*)&brv[0] = *(const float4*)(bres + o0);
    *(float4*)&brv[4] = *(const float4*)(bres + o0 + 4);

    float v[8];
    float sum = 0.f, sq = 0.f;
    #pragma unroll
    for (int j = 0; j < 8; j++) {
        int f = f0 + j;
        float c = w0 * s_agg[f] + w1 * s_agg[65 + f] + w2 * s_agg[130 + f] + w3 * s_agg[195 + f];
        c += cbv[j] + res[j] + brv[j];
        v[j] = c;
        sum += c;
        sq = fmaf(c, c, sq);
    }

    #pragma unroll
    for (int off = 16; off; off >>= 1) {
        sum += __shfl_xor_sync(0xffffffffu, sum, off);
        sq  += __shfl_xor_sync(0xffffffffu, sq, off);
    }
    if ((t & 31) == 0) { s_red[t >> 5] = sum; s_red[2 + (t >> 5)] = sq; }
    __syncthreads();
    sum = s_red[0] + s_red[1];
    sq  = s_red[2] + s_red[3];

    float mean = sum * (1.0f / 512.0f);
    float var  = sq * (1.0f / 512.0f) - mean * mean;
    float rstd = rsqrtf(var + 1e-5f);

    float gm[8], bt[8], o[8];
    *(float4*)&gm[0] = *(const float4*)(gamma + o0);
    *(float4*)&gm[4] = *(const float4*)(gamma + o0 + 4);
    *(float4*)&bt[0] = *(const float4*)(beta + o0);
    *(float4*)&bt[4] = *(const float4*)(beta + o0 + 4);
    #pragma unroll
    for (int j = 0; j < 8; j++)
        o[j] = fmaxf(0.f, (v[j] - mean) * rstd * gm[j] + bt[j]);
    float* op = out + (size_t)n * 512 + o0;
    *(float4*)op       = *(float4*)&o[0];
    *(float4*)(op + 4) = *(float4*)&o[4];
}

// ---------------- launch (round-8 fork/join, graph-capturable) ----------------
extern "C" void kernel_launch(void* const* d_in, const int* in_sizes, int n_in,
                              void* d_out, int out_size) {
    const float* x  = (const float*)d_in[0];
    const int*   ei = (const int*)d_in[1];
    const float* Wb = (const float*)d_in[2];
    const float* Wc = (const float*)d_in[3];
    const float* bc = (const float*)d_in[4];
    const float* cb = (const float*)d_in[5];
    const float* Wr = (const float*)d_in[6];
    const float* br = (const float*)d_in[7];
    const float* gm = (const float*)d_in[8];
    const float* bt = (const float*)d_in[9];
    float* out = (float*)d_out;

    static cudaStream_t s1 = nullptr, s2 = nullptr;
    static cudaEvent_t  ev0 = nullptr, evP = nullptr, ev1 = nullptr, ev2 = nullptr;
    static bool init = false;
    if (!init) {
        cudaStreamCreateWithFlags(&s1, cudaStreamNonBlocking);
        cudaStreamCreateWithFlags(&s2, cudaStreamNonBlocking);
        cudaEventCreateWithFlags(&ev0, cudaEventDisableTiming);
        cudaEventCreateWithFlags(&evP, cudaEventDisableTiming);
        cudaEventCreateWithFlags(&ev1, cudaEventDisableTiming);
        cudaEventCreateWithFlags(&ev2, cudaEventDisableTiming);
        cudaFuncSetAttribute(k_gemm_mma,  cudaFuncAttributeMaxDynamicSharedMemorySize, GEMM_SMEM);
        cudaFuncSetAttribute(k_gemm_tail, cudaFuncAttributeMaxDynamicSharedMemorySize, TAIL_SMEM);
        init = true;
    }

    // fork: s1 = packT -> tail, s2 = prep chain
    cudaEventRecord(ev0, 0);
    cudaStreamWaitEvent(s1, ev0, 0);
    cudaStreamWaitEvent(s2, ev0, 0);

    k_packT<<<(800 * KIN + 255) / 256, 256, 0, s1>>>(Wb, Wc, Wr);           // idx 0
    cudaEventRecord(evP, s1);

    k_split<<<(NN * KIN / 4 + 255) / 256, 256>>>(x);                        // idx 1 (main)
    k_gemm_tail<<<(NN + BM - 1) / BM, 256, TAIL_SMEM, s1>>>(x);             // idx 2 (s1)

    cudaStreamWaitEvent(0, evP, 0);
    dim3 gg(NTILES_N, (NN + BM - 1) / BM);
    k_gemm_mma<<<gg, 256, GEMM_SMEM>>>();                                   // idx 3 (main, profiled)

    k_zero<<<(NN + 255) / 256, 256, 0, s2>>>();                             // idx 4
    k_hist<<<(EE + 255) / 256, 256, 0, s2>>>(ei);                           // idx 5
    k_dinv<<<(NN + 255) / 256, 256, 0, s2>>>();                             // idx 6
    k_scan1<<<NBLK, 1024, 0, s2>>>();                                       // idx 7
    k_scan2<<<1, 64, 0, s2>>>();                                            // idx 8
    k_scan3<<<NBLK, 1024, 0, s2>>>();                                       // idx 9
    k_fill<<<(EE + 255) / 256, 256, 0, s2>>>(ei);                           // idx 10

    // join
    cudaEventRecord(ev1, s1);
    cudaEventRecord(ev2, s2);
    cudaStreamWaitEvent(0, ev1, 0);
    cudaStreamWaitEvent(0, ev2, 0);

    k_fused<<<NN, 64>>>(bc, cb, br, gm, bt, out);                           // idx 11
}

// round 13
// speedup vs baseline: 1.7216x; 1.6166x over previous
#include <cuda_runtime.h>
#include <cuda_fp16.h>
#include <cstdint>

#define NN   50000
#define EE   800000
#define KIN  512
#define NBLK 49

#define PB 256              // bases cols (fp16 slab)
#define PR 544              // rest: [0,32) comb | [32,544) res (fp32)

#define BM 128
#define BN 128
#define BK 64               // 64 fp16 = 128B rows (SW128)
#define NKT (KIN / BK)      // 8
#define NTILES_N 6
#define STAGE_B 32768       // A 16K + B 16K
#define GEMM_SMEM (3 * STAGE_B)

// tail GEMM (cols 768..800), fp16 single-product
#define T_A 0
#define T_B 16384
#define T_STAGE 20480
#define TAIL_SMEM (2 * T_STAGE)

// ---------------- static device scratch ----------------
__device__ __half g_bases_h[(size_t)NN * PB];           // 25.6 MB fp16 gather slab
__device__ float g_rest[(size_t)NN * PR];
__device__ __half g_xh[(size_t)NN * KIN];               // 51.2 MB fp16 x
__device__ __half g_WhT[(size_t)800 * KIN];             // fp16 packed+transposed W
__device__ float g_dinv[NN];
__device__ int   g_hist[NN];
__device__ int   g_rowstart[NN + 1];
__device__ int   g_cursor[NN];
__device__ int   g_csr[EE];
__device__ int   g_part[64];

// ---------------- helpers ----------------
__device__ __forceinline__ uint32_t smem_u32(const void* p) {
    uint32_t a;
    asm("{ .reg .u64 t; cvta.to.shared.u64 t, %1; cvt.u32.u64 %0, t; }" : "=r"(a) : "l"(p));
    return a;
}
__device__ __forceinline__ void ldmx4(uint32_t& r0, uint32_t& r1, uint32_t& r2, uint32_t& r3, uint32_t addr) {
    asm volatile("ldmatrix.sync.aligned.m8n8.x4.shared.b16 {%0,%1,%2,%3}, [%4];"
                 : "=r"(r0), "=r"(r1), "=r"(r2), "=r"(r3) : "r"(addr));
}
__device__ __forceinline__ void mma16816h(float* c, const uint32_t* a, const uint32_t* b) {
    asm volatile(
        "mma.sync.aligned.m16n8k16.row.col.f32.f16.f16.f32 "
        "{%0,%1,%2,%3}, {%4,%5,%6,%7}, {%8,%9}, {%0,%1,%2,%3};"
        : "+f"(c[0]), "+f"(c[1]), "+f"(c[2]), "+f"(c[3])
        : "r"(a[0]), "r"(a[1]), "r"(a[2]), "r"(a[3]), "r"(b[0]), "r"(b[1]));
}
__device__ __forceinline__ void cpasync16(uint32_t dst, const void* src, bool pred) {
    int sz = pred ? 16 : 0;
    asm volatile("cp.async.cg.shared.global [%0], [%1], 16, %2;"
                 :: "r"(dst), "l"(src), "r"(sz) : "memory");
}
// 8 fp32 -> 8 fp16 packed in uint4
__device__ __forceinline__ uint4 tohalf8(const float* f) {
    __half2 h0 = __float22half2_rn(make_float2(f[0], f[1]));
    __half2 h1 = __float22half2_rn(make_float2(f[2], f[3]));
    __half2 h2 = __float22half2_rn(make_float2(f[4], f[5]));
    __half2 h3 = __float22half2_rn(make_float2(f[6], f[7]));
    return make_uint4(*(uint32_t*)&h0, *(uint32_t*)&h1, *(uint32_t*)&h2, *(uint32_t*)&h3);
}

// ---------------- graph prep ----------------
__global__ void k_zero() {
    int i = blockIdx.x * blockDim.x + threadIdx.x;
    if (i < NN) { g_hist[i] = 0; g_cursor[i] = 0; }
}
__global__ void k_hist(const int* __restrict__ ei) {
    int e = blockIdx.x * blockDim.x + threadIdx.x;
    if (e < EE) atomicAdd(&g_hist[ei[EE + e]], 1);
}
__global__ void k_dinv() {
    int i = blockIdx.x * blockDim.x + threadIdx.x;
    if (i < NN) g_dinv[i] = rsqrtf((float)(g_hist[i] + 1));
}
__global__ void k_scan1() {
    __shared__ int s[1024];
    int b = blockIdx.x, t = threadIdx.x, i = b * 1024 + t;
    int v = (i < NN) ? g_hist[i] : 0;
    int x = v; s[t] = x; __syncthreads();
    #pragma unroll
    for (int off = 1; off < 1024; off <<= 1) {
        int tmp = (t >= off) ? s[t - off] : 0;
        __syncthreads();
        x += tmp; s[t] = x;
        __syncthreads();
    }
    if (i < NN) g_rowstart[i] = x - v;
    if (t == 1023) g_part[b] = x;
}
__global__ void k_scan2() {
    __shared__ int s[64];
    int t = threadIdx.x;
    int v = (t < NBLK) ? g_part[t] : 0;
    int x = v; s[t] = x; __syncthreads();
    #pragma unroll
    for (int off = 1; off < 64; off <<= 1) {
        int tmp = (t >= off) ? s[t - off] : 0;
        __syncthreads();
        x += tmp; s[t] = x;
        __syncthreads();
    }
    if (t < NBLK) g_part[t] = x - v;
    if (t == 63) g_rowstart[NN] = s[63];
}
__global__ void k_scan3() {
    int b = blockIdx.x, i = b * 1024 + threadIdx.x;
    if (i < NN) g_rowstart[i] += g_part[b];
}
__global__ void k_fill(const int* __restrict__ ei) {
    int e = blockIdx.x * blockDim.x + threadIdx.x;
    if (e < EE) {
        int d = ei[EE + e];
        int p = atomicAdd(&g_cursor[d], 1);
        g_csr[g_rowstart[d] + p] = ei[e];
    }
}
__global__ void k_packT(const float* __restrict__ Wb, const float* __restrict__ Wc,
                        const float* __restrict__ Wr) {
    int idx = blockIdx.x * blockDim.x + threadIdx.x;
    if (idx >= 800 * KIN) return;
    int n = idx / KIN, k = idx % KIN;
    float v;
    if (n < 256)      v = Wb[k * 256 + n];
    else if (n < 288) v = Wc[k * 32 + (n - 256)];
    else              v = Wr[k * 512 + (n - 288)];
    g_WhT[idx] = __float2half(v);
}
__global__ void k_split(const float* __restrict__ x) {
    size_t i = (size_t)blockIdx.x * blockDim.x + threadIdx.x;
    if (i >= (size_t)NN * KIN / 4) return;
    float4 v = ((const float4*)x)[i];
    __half2 h0 = __float22half2_rn(make_float2(v.x, v.y));
    __half2 h1 = __float22half2_rn(make_float2(v.z, v.w));
    ((uint2*)g_xh)[i] = make_uint2(*(uint32_t*)&h0, *(uint32_t*)&h1);
}

// ---------------- main fp16 HMMA GEMM: cols [0,768), BK=64, cp.async 3-stage ----------------
// cols [0,256) -> g_bases_h (fp16), cols [256,768) -> g_rest[0,512) (fp32)
__global__ void __launch_bounds__(256, 2) k_gemm_mma() {
    extern __shared__ char smem[];
    uint32_t sb = smem_u32(smem);
    int tid = threadIdx.x, wid = tid >> 5, lane = tid & 31;
    int m0 = blockIdx.y * BM, n0 = blockIdx.x * BN;
    int wm = wid & 1, wn = wid >> 1;

    float acc[4][4][4];
    #pragma unroll
    for (int i = 0; i < 4; i++)
        #pragma unroll
        for (int j = 0; j < 4; j++)
            #pragma unroll
            for (int q = 0; q < 4; q++) acc[i][j][q] = 0.f;

    int sr = tid >> 3, sc = tid & 7;
    int koff = sc * 8;
    uint32_t st_off[4];
    bool arow_ok[4];
    #pragma unroll
    for (int i = 0; i < 4; i++) {
        int r = sr + i * 32;
        st_off[i] = (uint32_t)(r * 128 + ((sc ^ (r & 7)) * 16));
        arow_ok[i] = (m0 + r) < NN;
    }

    int a_row[4];
    #pragma unroll
    for (int mt = 0; mt < 4; mt++) a_row[mt] = wm * 64 + mt * 16 + (lane & 15);
    int a_lc = lane >> 4;
    int b_row0 = wn * 32 + ((lane >> 4) << 3) + (lane & 7);
    int b_row1 = b_row0 + 16;
    int b_lc = (lane >> 3) & 1;

    auto issue = [&](int s, int buf) {
        int k0 = s * BK;
        uint32_t base = sb + buf * STAGE_B;
        #pragma unroll
        for (int i = 0; i < 4; i++) {
            const void* src = g_xh + (size_t)(m0 + sr + i * 32) * KIN + k0 + koff;
            cpasync16(base + st_off[i], src, arow_ok[i]);
        }
        #pragma unroll
        for (int i = 0; i < 4; i++) {
            const void* src = g_WhT + (size_t)(n0 + sr + i * 32) * KIN + k0 + koff;
            cpasync16(base + 16384 + st_off[i], src, true);
        }
        asm volatile("cp.async.commit_group;" ::: "memory");
    };

    issue(0, 0);
    issue(1, 1);

    int cbuf = 0, nbuf = 2;
    #pragma unroll 1
    for (int kt = 0; kt < NKT; kt++) {
        if (kt < NKT - 1) asm volatile("cp.async.wait_group 1;" ::: "memory");
        else              asm volatile("cp.async.wait_group 0;" ::: "memory");
        __syncthreads();

        if (kt + 2 < NKT) {
            issue(kt + 2, nbuf);
        } else {
            asm volatile("cp.async.commit_group;" ::: "memory");
        }

        uint32_t ab = sb + cbuf * STAGE_B;
        uint32_t bb = ab + 16384;

        #pragma unroll
        for (int g = 0; g < 4; g++) {               // 4 k16 groups per BK=64 stage
            uint32_t bf[8];
            {
                int ch = g * 2 + b_lc;
                uint32_t o0 = (uint32_t)(b_row0 * 128 + ((ch ^ (b_row0 & 7)) * 16));
                uint32_t o1 = (uint32_t)(b_row1 * 128 + ((ch ^ (b_row1 & 7)) * 16));
                ldmx4(bf[0], bf[1], bf[2], bf[3], bb + o0);
                ldmx4(bf[4], bf[5], bf[6], bf[7], bb + o1);
            }
            #pragma unroll
            for (int mt = 0; mt < 4; mt++) {
                uint32_t af[4];
                int r = a_row[mt];
                int ch = g * 2 + a_lc;
                uint32_t oh = (uint32_t)(r * 128 + ((ch ^ (r & 7)) * 16));
                ldmx4(af[0], af[1], af[2], af[3], ab + oh);
                #pragma unroll
                for (int nt = 0; nt < 4; nt++)
                    mma16816h(acc[mt][nt], af, &bf[nt * 2]);
            }
        }

        cbuf = (cbuf == 2) ? 0 : cbuf + 1;
        nbuf = (nbuf == 2) ? 0 : nbuf + 1;
    }

    int gid = lane >> 2, tig = lane & 3;
    if (n0 < 256) {
        #pragma unroll
        for (int mt = 0; mt < 4; mt++) {
            int row0 = m0 + wm * 64 + mt * 16 + gid;
            #pragma unroll
            for (int nt = 0; nt < 4; nt++) {
                int col = n0 + wn * 32 + nt * 8 + 2 * tig;
                __half2 p0 = __float22half2_rn(make_float2(acc[mt][nt][0], acc[mt][nt][1]));
                __half2 p1 = __float22half2_rn(make_float2(acc[mt][nt][2], acc[mt][nt][3]));
                if (row0 < NN)
                    *(uint32_t*)(g_bases_h + (size_t)row0 * PB + col) = *(uint32_t*)&p0;
                if (row0 + 8 < NN)
                    *(uint32_t*)(g_bases_h + (size_t)(row0 + 8) * PB + col) = *(uint32_t*)&p1;
            }
        }
    } else {
        int c0 = n0 - 256;
        #pragma unroll
        for (int mt = 0; mt < 4; mt++) {
            int row0 = m0 + wm * 64 + mt * 16 + gid;
            #pragma unroll
            for (int nt = 0; nt < 4; nt++) {
                int col = c0 + wn * 32 + nt * 8 + 2 * tig;
                if (row0 < NN)
                    *(float2*)(g_rest + (size_t)row0 * PR + col) = make_float2(acc[mt][nt][0], acc[mt][nt][1]);
                if (row0 + 8 < NN)
                    *(float2*)(g_rest + (size_t)(row0 + 8) * PR + col) = make_float2(acc[mt][nt][2], acc[mt][nt][3]);
            }
        }
    }
}

// ---------------- tail fp16 GEMM: orig cols [768,800) -> g_rest cols [512,544) ----------------
__global__ void __launch_bounds__(256, 2) k_gemm_tail(const float* __restrict__ x) {
    extern __shared__ char smem[];
    uint32_t sb = smem_u32(smem);
    int tid = threadIdx.x, wid = tid >> 5, lane = tid & 31;
    int m0 = blockIdx.x * BM;
    const int n0 = 768;
    int wm = wid & 1, wn = wid >> 1;

    float acc[4][4];
    #pragma unroll
    for (int i = 0; i < 4; i++)
        #pragma unroll
        for (int q = 0; q < 4; q++) acc[i][q] = 0.f;

    int sr = tid >> 3, sc = tid & 7;
    const bool arow_ok[4] = { (m0 + sr) < NN, (m0 + sr + 32) < NN,
                              (m0 + sr + 64) < NN, (m0 + sr + 96) < NN };
    uint32_t st_off[4];
    #pragma unroll
    for (int v = 0; v < 4; v++) {
        int r = sr + v * 32;
        st_off[v] = (uint32_t)(r * 128 + ((sc ^ (r & 7)) * 16));
    }
    uint32_t bst_off = (uint32_t)(sr * 128 + ((sc ^ (sr & 7)) * 16));

    int a_row[4];
    #pragma unroll
    for (int mt = 0; mt < 4; mt++) a_row[mt] = wm * 64 + mt * 16 + (lane & 15);
    int a_lc = lane >> 4;
    int b_rw = wn * 8 + (lane & 7);
    int b_ms = lane >> 3;

    {   // prologue stage 0 (k 0..63)
        #pragma unroll
        for (int v = 0; v < 4; v++) {
            float f[8];
            if (arow_ok[v]) {
                const float* p = x + (size_t)(m0 + sr + v * 32) * KIN + sc * 8;
                *(float4*)&f[0] = *(const float4*)p;
                *(float4*)&f[4] = *(const float4*)(p + 4);
            } else {
                #pragma unroll
                for (int q = 0; q < 8; q++) f[q] = 0.f;
            }
            *(uint4*)(smem + T_A + st_off[v]) = tohalf8(f);
        }
        size_t off = (size_t)(n0 + sr) * KIN + sc * 8;
        *(uint4*)(smem + T_B + bst_off) = *(const uint4*)(g_WhT + off);
    }
    __syncthreads();

    #pragma unroll 1
    for (int kt = 0; kt < KIN / 64; kt++) {
        int cur = kt & 1;
        bool more = (kt + 1) < (KIN / 64);

        float pa[4][8];
        uint4 pb;
        if (more) {
            int k0 = (kt + 1) * 64;
            #pragma unroll
            for (int v = 0; v < 4; v++) {
                if (arow_ok[v]) {
                    const float* p = x + (size_t)(m0 + sr + v * 32) * KIN + k0 + sc * 8;
                    *(float4*)&pa[v][0] = *(const float4*)p;
                    *(float4*)&pa[v][4] = *(const float4*)(p + 4);
                } else {
                    #pragma unroll
                    for (int q = 0; q < 8; q++) pa[v][q] = 0.f;
                }
            }
            size_t off = (size_t)(n0 + sr) * KIN + k0 + sc * 8;
            pb = *(const uint4*)(g_WhT + off);
        }

        uint32_t a_b = sb + cur * T_STAGE + T_A;
        uint32_t b_b = sb + cur * T_STAGE + T_B;

        #pragma unroll
        for (int p = 0; p < 2; p++) {
            uint32_t bf[4];
            uint32_t boff = (uint32_t)(b_rw * 128 + (((4 * p + b_ms) ^ (b_rw & 7)) * 16));
            ldmx4(bf[0], bf[1], bf[2], bf[3], b_b + boff);
            #pragma unroll
            for (int s = 0; s < 2; s++) {
                int k16 = 2 * p + s;
                #pragma unroll
                for (int mt = 0; mt < 4; mt++) {
                    uint32_t af[4];
                    int r = a_row[mt];
                    uint32_t off = (uint32_t)(r * 128 + (((k16 * 2 + a_lc) ^ (r & 7)) * 16));
                    ldmx4(af[0], af[1], af[2], af[3], a_b + off);
                    mma16816h(acc[mt], af, &bf[2 * s]);
                }
            }
        }

        if (more) {
            char* dst = smem + (cur ^ 1) * T_STAGE;
            #pragma unroll
            for (int v = 0; v < 4; v++)
                *(uint4*)(dst + T_A + st_off[v]) = tohalf8(pa[v]);
            *(uint4*)(dst + T_B + bst_off) = pb;
        }
        __syncthreads();
    }

    int gid = lane >> 2, tig = lane & 3;
    #pragma unroll
    for (int mt = 0; mt < 4; mt++) {
        int row0 = m0 + wm * 64 + mt * 16 + gid;
        int col = 512 + wn * 8 + 2 * tig;
        if (row0 < NN)
            *(float2*)(g_rest + (size_t)row0 * PR + col) = make_float2(acc[mt][0], acc[mt][1]);
        if (row0 + 8 < NN)
            *(float2*)(g_rest + (size_t)(row0 + 8) * PR + col) = make_float2(acc[mt][2], acc[mt][3]);
    }
}

// ---------------- fused gather (fp16 bases) + combine + residual + LN + ReLU (64 thr/node) ----------------
__global__ void __launch_bounds__(64) k_fused(
    const float* __restrict__ bcomb, const float* __restrict__ convb,
    const float* __restrict__ bres,  const float* __restrict__ gamma,
    const float* __restrict__ beta,  float* __restrict__ out)
{
    int n = blockIdx.x;
    int t = threadIdx.x;

    __shared__ float s_agg[4 * 65];
    __shared__ float s_w[32];
    __shared__ int   s_src[64];
    __shared__ float s_wt[64];
    __shared__ float s_red[4];

    float dn = g_dinv[n];
    const __half* Bn = g_bases_h + (size_t)n * PB;
    const float* Rn = g_rest + (size_t)n * PR;

    float4 acc;
    {
        uint2 u = *(const uint2*)(Bn + 4 * t);
        float2 f0 = __half22float2(*(__half2*)&u.x);
        float2 f1 = __half22float2(*(__half2*)&u.y);
        float dn2 = dn * dn;
        acc.x = f0.x * dn2; acc.y = f0.y * dn2;
        acc.z = f1.x * dn2; acc.w = f1.y * dn2;
    }

    int start = g_rowstart[n];
    int end   = g_rowstart[n + 1];
    for (int base = start; base < end; base += 64) {
        int cnt = min(64, end - base);
        if (t < cnt) {
            int s = g_csr[base + t];
            s_src[t] = s;
            s_wt[t]  = g_dinv[s] * dn;
        }
        __syncthreads();
        int j = 0;
        for (; j + 4 <= cnt; j += 4) {
            uint2 u0 = *(const uint2*)(g_bases_h + (size_t)s_src[j]     * PB + 4 * t);
            uint2 u1 = *(const uint2*)(g_bases_h + (size_t)s_src[j + 1] * PB + 4 * t);
            uint2 u2 = *(const uint2*)(g_bases_h + (size_t)s_src[j + 2] * PB + 4 * t);
            uint2 u3 = *(const uint2*)(g_bases_h + (size_t)s_src[j + 3] * PB + 4 * t);
            float w0 = s_wt[j], w1 = s_wt[j + 1], w2 = s_wt[j + 2], w3 = s_wt[j + 3];
            float2 a, b;
            a = __half22float2(*(__half2*)&u0.x);
            b = __half22float2(*(__half2*)&u0.y);
            acc.x = fmaf(a.x, w0, acc.x); acc.y = fmaf(a.y, w0, acc.y);
            acc.z = fmaf(b.x, w0, acc.z); acc.w = fmaf(b.y, w0, acc.w);
            a = __half22float2(*(__half2*)&u1.x);
            b = __half22float2(*(__half2*)&u1.y);
            acc.x = fmaf(a.x, w1, acc.x); acc.y = fmaf(a.y, w1, acc.y);
            acc.z = fmaf(b.x, w1, acc.z); acc.w = fmaf(b.y, w1, acc.w);
            a = __half22float2(*(__half2*)&u2.x);
            b = __half22float2(*(__half2*)&u2.y);
            acc.x = fmaf(a.x, w2, acc.x); acc.y = fmaf(a.y, w2, acc.y);
            acc.z = fmaf(b.x, w2, acc.z); acc.w = fmaf(b.y, w2, acc.w);
            a = __half22float2(*(__half2*)&u3.x);
            b = __half22float2(*(__half2*)&u3.y);
            acc.x = fmaf(a.x, w3, acc.x); acc.y = fmaf(a.y, w3, acc.y);
            acc.z = fmaf(b.x, w3, acc.z); acc.w = fmaf(b.y, w3, acc.w);
        }
        for (; j < cnt; j++) {
            uint2 u = *(const uint2*)(g_bases_h + (size_t)s_src[j] * PB + 4 * t);
            float w = s_wt[j];
            float2 a = __half22float2(*(__half2*)&u.x);
            float2 b = __half22float2(*(__half2*)&u.y);
            acc.x = fmaf(a.x, w, acc.x); acc.y = fmaf(a.y, w, acc.y);
            acc.z = fmaf(b.x, w, acc.z); acc.w = fmaf(b.y, w, acc.w);
        }
        __syncthreads();
    }

    {
        int c0 = t * 4, b = c0 >> 6, f = c0 & 63;
        float* p = &s_agg[b * 65 + f];
        p[0] = acc.x; p[1] = acc.y; p[2] = acc.z; p[3] = acc.w;
    }
    if (t < 32) s_w[t] = Rn[t] + bcomb[t];
    __syncthreads();

    int o0 = t * 8;
    int h  = t >> 3;
    int f0 = (t & 7) * 8;
    float w0 = s_w[h * 4 + 0], w1 = s_w[h * 4 + 1];
    float w2 = s_w[h * 4 + 2], w3 = s_w[h * 4 + 3];

    float res[8], cbv[8], brv[8];
    *(float4*)&res[0] = *(const float4*)(Rn + 32 + o0);
    *(float4*)&res[4] = *(const float4*)(Rn + 32 + o0 + 4);
    *(float4*)&cbv[0] = *(const float4*)(convb + o0);
    *(float4*)&cbv[4] = *(const float4*)(convb + o0 + 4);
    *(float4*)&brv[0] = *(const float4*)(bres + o0);
    *(float4*)&brv[4] = *(const float4*)(bres + o0 + 4);

    float v[8];
    float sum = 0.f, sq = 0.f;
    #pragma unroll
    for (int j = 0; j < 8; j++) {
        int f = f0 + j;
        float c = w0 * s_agg[f] + w1 * s_agg[65 + f] + w2 * s_agg[130 + f] + w3 * s_agg[195 + f];
        c += cbv[j] + res[j] + brv[j];
        v[j] = c;
        sum += c;
        sq = fmaf(c, c, sq);
    }

    #pragma unroll
    for (int off = 16; off; off >>= 1) {
        sum += __shfl_xor_sync(0xffffffffu, sum, off);
        sq  += __shfl_xor_sync(0xffffffffu, sq, off);
    }
    if ((t & 31) == 0) { s_red[t >> 5] = sum; s_red[2 + (t >> 5)] = sq; }
    __syncthreads();
    sum = s_red[0] + s_red[1];
    sq  = s_red[2] + s_red[3];

    float mean = sum * (1.0f / 512.0f);
    float var  = sq * (1.0f / 512.0f) - mean * mean;
    float rstd = rsqrtf(var + 1e-5f);

    float gm[8], bt[8], o[8];
    *(float4*)&gm[0] = *(const float4*)(gamma + o0);
    *(float4*)&gm[4] = *(const float4*)(gamma + o0 + 4);
    *(float4*)&bt[0] = *(const float4*)(beta + o0);
    *(float4*)&bt[4] = *(const float4*)(beta + o0 + 4);
    #pragma unroll
    for (int j = 0; j < 8; j++)
        o[j] = fmaxf(0.f, (v[j] - mean) * rstd * gm[j] + bt[j]);
    float* op = out + (size_t)n * 512 + o0;
    *(float4*)op       = *(float4*)&o[0];
    *(float4*)(op + 4) = *(float4*)&o[4];
}

// ---------------- launch (round-8 fork/join, graph-capturable) ----------------
extern "C" void kernel_launch(void* const* d_in, const int* in_sizes, int n_in,
                              void* d_out, int out_size) {
    const float* x  = (const float*)d_in[0];
    const int*   ei = (const int*)d_in[1];
    const float* Wb = (const float*)d_in[2];
    const float* Wc = (const float*)d_in[3];
    const float* bc = (const float*)d_in[4];
    const float* cb = (const float*)d_in[5];
    const float* Wr = (const float*)d_in[6];
    const float* br = (const float*)d_in[7];
    const float* gm = (const float*)d_in[8];
    const float* bt = (const float*)d_in[9];
    float* out = (float*)d_out;

    static cudaStream_t s1 = nullptr, s2 = nullptr;
    static cudaEvent_t  ev0 = nullptr, evP = nullptr, ev1 = nullptr, ev2 = nullptr;
    static bool init = false;
    if (!init) {
        cudaStreamCreateWithFlags(&s1, cudaStreamNonBlocking);
        cudaStreamCreateWithFlags(&s2, cudaStreamNonBlocking);
        cudaEventCreateWithFlags(&ev0, cudaEventDisableTiming);
        cudaEventCreateWithFlags(&evP, cudaEventDisableTiming);
        cudaEventCreateWithFlags(&ev1, cudaEventDisableTiming);
        cudaEventCreateWithFlags(&ev2, cudaEventDisableTiming);
        cudaFuncSetAttribute(k_gemm_mma,  cudaFuncAttributeMaxDynamicSharedMemorySize, GEMM_SMEM);
        cudaFuncSetAttribute(k_gemm_tail, cudaFuncAttributeMaxDynamicSharedMemorySize, TAIL_SMEM);
        init = true;
    }

    // fork: s1 = packT -> tail, s2 = prep chain
    cudaEventRecord(ev0, 0);
    cudaStreamWaitEvent(s1, ev0, 0);
    cudaStreamWaitEvent(s2, ev0, 0);

    k_packT<<<(800 * KIN + 255) / 256, 256, 0, s1>>>(Wb, Wc, Wr);           // idx 0
    cudaEventRecord(evP, s1);

    k_split<<<(NN * KIN / 4 + 255) / 256, 256>>>(x);                        // idx 1 (main)
    k_gemm_tail<<<(NN + BM - 1) / BM, 256, TAIL_SMEM, s1>>>(x);             // idx 2 (s1)

    cudaStreamWaitEvent(0, evP, 0);
    dim3 gg(NTILES_N, (NN + BM - 1) / BM);
    k_gemm_mma<<<gg, 256, GEMM_SMEM>>>();                                   // idx 3 (main, profiled)

    k_zero<<<(NN + 255) / 256, 256, 0, s2>>>();                             // idx 4
    k_hist<<<(EE + 255) / 256, 256, 0, s2>>>(ei);                           // idx 5
    k_dinv<<<(NN + 255) / 256, 256, 0, s2>>>();                             // idx 6
    k_scan1<<<NBLK, 1024, 0, s2>>>();                                       // idx 7
    k_scan2<<<1, 64, 0, s2>>>();                                            // idx 8
    k_scan3<<<NBLK, 1024, 0, s2>>>();                                       // idx 9
    k_fill<<<(EE + 255) / 256, 256, 0, s2>>>(ei);                           // idx 10

    // join
    cudaEventRecord(ev1, s1);
    cudaEventRecord(ev2, s2);
    cudaStreamWaitEvent(0, ev1, 0);
    cudaStreamWaitEvent(0, ev2, 0);

    k_fused<<<NN, 64>>>(bc, cb, br, gm, bt, out);                           // idx 11
}